// round 1
// baseline (speedup 1.0000x reference)
#include <cuda_runtime.h>
#include <cstdint>

// ---------------------------------------------------------------------------
// Problem constants
// ---------------------------------------------------------------------------
static constexpr int B   = 8;
static constexpr int S   = 1024;
static constexpr int D   = 1024;
static constexpr int H   = 16;
static constexpr int DH  = 64;
static constexpr int R   = 128;   // RANK
static constexpr int KC  = 16;
static constexpr int KE  = 8;

// ---------------------------------------------------------------------------
// Device scratch (no cudaMalloc allowed). ~148 MB.
// Layout (floats):
//   Wc   [B][D][R]      1,048,576
//   h    [B][S][R]      1,048,576
//   Wq   [B][R][D]      1,048,576
//   Wk   [B][R][D]      1,048,576
//   Wv   [B][R][D]      1,048,576
//   Q    [B][S][D]      8,388,608
//   K    [B][S][D]      8,388,608
//   V    [B][S][D]      8,388,608
//   AO   [B][S][D]      8,388,608
// ---------------------------------------------------------------------------
static constexpr size_t N_WC  = (size_t)B * D * R;
static constexpr size_t N_H   = (size_t)B * S * R;
static constexpr size_t N_WX  = (size_t)B * R * D;
static constexpr size_t N_QKV = (size_t)B * S * D;
static constexpr size_t SCRATCH_FLOATS = N_WC + N_H + 3 * N_WX + 4 * N_QKV;

__device__ float g_scratch[SCRATCH_FLOATS];

// ---------------------------------------------------------------------------
// Kernel 1: Wc[b,d,r] = sum_k w[b,k] * compress_neurons[idx[b,k]][d][r]
// grid: B*D blocks, 128 threads (one per r)
// ---------------------------------------------------------------------------
__global__ void combine_compress_kernel(const float* __restrict__ w,
                                        const int*   __restrict__ idx,
                                        const float* __restrict__ cn,
                                        float*       __restrict__ Wc)
{
    int b = blockIdx.x >> 10;
    int d = blockIdx.x & 1023;
    int r = threadIdx.x;

    __shared__ float sw[KC];
    __shared__ int   si[KC];
    if (r < KC) { sw[r] = w[b * KC + r]; si[r] = idx[b * KC + r]; }
    __syncthreads();

    float acc = 0.f;
#pragma unroll
    for (int k = 0; k < KC; k++)
        acc += sw[k] * cn[((long)si[k] * D + d) * R + r];

    Wc[((long)b * D + d) * R + r] = acc;
}

// ---------------------------------------------------------------------------
// Kernel 2: Wx[b,r,d] = sum_k w[b,k] * expand_pool[idx[b,k]][r][d]
// grid: (B*R, 3) blocks, 256 threads, float4 over d
// ---------------------------------------------------------------------------
__global__ void combine_expand_kernel(const float* __restrict__ wq, const int* __restrict__ iq,
                                      const float* __restrict__ wk, const int* __restrict__ ik,
                                      const float* __restrict__ wv, const int* __restrict__ iv,
                                      const float* __restrict__ pool,
                                      float* __restrict__ Wq, float* __restrict__ Wk,
                                      float* __restrict__ Wv)
{
    int mat = blockIdx.y;
    int br  = blockIdx.x;
    int b   = br >> 7;
    int r   = br & 127;

    const float* w   = (mat == 0) ? wq : (mat == 1) ? wk : wv;
    const int*   id  = (mat == 0) ? iq : (mat == 1) ? ik : iv;
    float*       out = (mat == 0) ? Wq : (mat == 1) ? Wk : Wv;

    __shared__ float sw[KE];
    __shared__ int   si[KE];
    int tid = threadIdx.x;
    if (tid < KE) { sw[tid] = w[b * KE + tid]; si[tid] = id[b * KE + tid]; }
    __syncthreads();

    int d0 = tid * 4;
    float4 acc = make_float4(0.f, 0.f, 0.f, 0.f);
#pragma unroll
    for (int k = 0; k < KE; k++) {
        float4 v = *(const float4*)&pool[((long)si[k] * R + r) * D + d0];
        float ww = sw[k];
        acc.x += ww * v.x; acc.y += ww * v.y;
        acc.z += ww * v.z; acc.w += ww * v.w;
    }
    *(float4*)&out[((long)b * R + r) * D + d0] = acc;
}

// ---------------------------------------------------------------------------
// Shared batched SGEMM: C[M,N] = A[M,K] @ B[K,N]   (or @ B[N,K]^T when TRANSB)
// BM=128, BN=64, BK=16, 256 threads, 8x4 micro-tile.
// All dims are exact multiples of the tiles for every call site.
// ---------------------------------------------------------------------------
template <bool TRANSB>
__global__ void __launch_bounds__(256, 4)
sgemm_kernel(const float* __restrict__ A, const float* __restrict__ Bm,
             float* __restrict__ C,
             int M, int N, int K, int lda, int ldb, int ldc,
             long sA, long sB, long sC)
{
    constexpr int BM = 128, BN = 64, BK = 16, TM = 8, TN = 4;

    int batch = blockIdx.z;
    A  += (long)batch * sA;
    Bm += (long)batch * sB;
    C  += (long)batch * sC;

    __shared__ float As[BK][BM];   // transposed A tile
    __shared__ float Bs[BK][BN];

    int n0 = blockIdx.x * BN;
    int m0 = blockIdx.y * BM;

    int tid = threadIdx.x;
    int tx  = tid & 15;   // n direction (16)
    int ty  = tid >> 4;   // m direction (16)

    // A load mapping: each thread loads 2 float4 along k (rows aRow, aRow+64)
    int aRow = tid >> 2;          // 0..63
    int aK4  = (tid & 3) * 4;     // 0,4,8,12
    // B load mapping (normal): one float4 along n
    int bRow = tid >> 4;          // k (0..15)
    int bCol = (tid & 15) * 4;    // n
    // B load mapping (transposed source): float4 along k
    int tbN  = tid >> 2;          // 0..63
    int tbK4 = (tid & 3) * 4;

    float acc[TM][TN];
#pragma unroll
    for (int i = 0; i < TM; i++)
#pragma unroll
        for (int j = 0; j < TN; j++) acc[i][j] = 0.f;

    for (int k0 = 0; k0 < K; k0 += BK) {
        // --- load A tile (transposed into smem) ---
#pragma unroll
        for (int rr = 0; rr < 2; rr++) {
            int m = aRow + rr * 64;
            float4 v = *(const float4*)&A[(long)(m0 + m) * lda + k0 + aK4];
            As[aK4 + 0][m] = v.x;
            As[aK4 + 1][m] = v.y;
            As[aK4 + 2][m] = v.z;
            As[aK4 + 3][m] = v.w;
        }
        // --- load B tile ---
        if (!TRANSB) {
            float4 v = *(const float4*)&Bm[(long)(k0 + bRow) * ldb + n0 + bCol];
            *(float4*)&Bs[bRow][bCol] = v;
        } else {
            float4 v = *(const float4*)&Bm[(long)(n0 + tbN) * ldb + k0 + tbK4];
            Bs[tbK4 + 0][tbN] = v.x;
            Bs[tbK4 + 1][tbN] = v.y;
            Bs[tbK4 + 2][tbN] = v.z;
            Bs[tbK4 + 3][tbN] = v.w;
        }
        __syncthreads();

#pragma unroll
        for (int kk = 0; kk < BK; kk++) {
            float a[TM], bb[TN];
            float4 a0 = *(const float4*)&As[kk][ty * TM + 0];
            float4 a1 = *(const float4*)&As[kk][ty * TM + 4];
            a[0] = a0.x; a[1] = a0.y; a[2] = a0.z; a[3] = a0.w;
            a[4] = a1.x; a[5] = a1.y; a[6] = a1.z; a[7] = a1.w;
            float4 b0 = *(const float4*)&Bs[kk][tx * TN];
            bb[0] = b0.x; bb[1] = b0.y; bb[2] = b0.z; bb[3] = b0.w;
#pragma unroll
            for (int i = 0; i < TM; i++)
#pragma unroll
                for (int j = 0; j < TN; j++)
                    acc[i][j] += a[i] * bb[j];
        }
        __syncthreads();
    }

    // --- store ---
#pragma unroll
    for (int i = 0; i < TM; i++) {
        float4 v = make_float4(acc[i][0], acc[i][1], acc[i][2], acc[i][3]);
        *(float4*)&C[(long)(m0 + ty * TM + i) * ldc + n0 + tx * TN] = v;
    }
}

// ---------------------------------------------------------------------------
// Kernel: causal flash attention, fp32.
// Q/K/V in [B,S,D] layout (head h occupies cols h*64..h*64+63).
// QT=32 query rows per block, KT=64 keys per tile, 256 threads (8 warps).
// Warp w owns query rows 4w..4w+3; lane owns head-dims {lane, lane+32} for O
// and key columns {lane, lane+32} for S.
// Smem = 8K(Q) + 16K(Kswz) + 16K(V) + 8K(P) = 49152 B exactly.
// ---------------------------------------------------------------------------
__global__ void __launch_bounds__(256)
flash_attn_kernel(const float* __restrict__ Q, const float* __restrict__ K,
                  const float* __restrict__ V, float* __restrict__ O)
{
    constexpr int QT = 32, KT = 64;

    __shared__ float4 Qs [QT][DH / 4];   // [row][d4], broadcast reads
    __shared__ float4 Ksw[KT][DH / 4];   // swizzled: [c][d4 ^ (c&7)]
    __shared__ float  Vs [KT][DH];       // [c][dh]
    __shared__ float  Ps [QT][KT];       // [row][c]

    int qt = blockIdx.x, h = blockIdx.y, b = blockIdx.z;
    int q0 = qt * QT;
    int tid = threadIdx.x, warp = tid >> 5, lane = tid & 31;

    const long bOff = (long)b * S * D;
    const float* Qg = Q + bOff + (long)q0 * D + h * DH;
    const float* Kg = K + bOff + h * DH;
    const float* Vg = V + bOff + h * DH;

    // load Q tile: 32 rows x 16 float4
    for (int i = tid; i < QT * (DH / 4); i += 256) {
        int r = i >> 4, d4 = i & 15;
        Qs[r][d4] = *(const float4*)&Qg[(long)r * D + d4 * 4];
    }

    float m[4], l[4], o0[4], o1[4];
#pragma unroll
    for (int i = 0; i < 4; i++) { m[i] = -1e30f; l[i] = 0.f; o0[i] = 0.f; o1[i] = 0.f; }

    int rbase = warp * 4;
    int nkt = q0 / KT + 1;
    const float scale = 0.125f;   // 1/sqrt(64)
    int c0 = lane, c1 = lane + 32;
    int swz = lane & 7;

    for (int kt = 0; kt < nkt; kt++) {
        __syncthreads();
        // load K/V tile: 64 rows x 16 float4 each
        for (int i = tid; i < KT * (DH / 4); i += 256) {
            int c = i >> 4, d4 = i & 15;
            long gro = (long)(kt * KT + c) * D + d4 * 4;
            Ksw[c][d4 ^ (c & 7)] = *(const float4*)&Kg[gro];
            *(float4*)&Vs[c][d4 * 4] = *(const float4*)&Vg[gro];
        }
        __syncthreads();

        // ---- S = Q K^T ----
        float s0[4], s1[4];
#pragma unroll
        for (int i = 0; i < 4; i++) { s0[i] = 0.f; s1[i] = 0.f; }
#pragma unroll
        for (int d4 = 0; d4 < DH / 4; d4++) {
            float4 k0v = Ksw[c0][d4 ^ swz];
            float4 k1v = Ksw[c1][d4 ^ swz];
#pragma unroll
            for (int i = 0; i < 4; i++) {
                float4 q = Qs[rbase + i][d4];
                s0[i] += q.x * k0v.x + q.y * k0v.y + q.z * k0v.z + q.w * k0v.w;
                s1[i] += q.x * k1v.x + q.y * k1v.y + q.z * k1v.z + q.w * k1v.w;
            }
        }

        bool lastTile = (kt == nkt - 1);
        // ---- online softmax (per row, warp-local) ----
#pragma unroll
        for (int i = 0; i < 4; i++) {
            int row = q0 + rbase + i;
            float v0 = s0[i] * scale;
            float v1 = s1[i] * scale;
            if (lastTile) {
                if (kt * KT + c0 > row) v0 = -1e30f;
                if (kt * KT + c1 > row) v1 = -1e30f;
            }
            float mt = fmaxf(v0, v1);
#pragma unroll
            for (int off = 16; off; off >>= 1)
                mt = fmaxf(mt, __shfl_xor_sync(0xffffffffu, mt, off));
            float mnew  = fmaxf(m[i], mt);
            float alpha = __expf(m[i] - mnew);
            float p0 = __expf(v0 - mnew);
            float p1 = __expf(v1 - mnew);
            float rs = p0 + p1;
#pragma unroll
            for (int off = 16; off; off >>= 1)
                rs += __shfl_xor_sync(0xffffffffu, rs, off);
            l[i] = l[i] * alpha + rs;
            m[i] = mnew;
            o0[i] *= alpha;
            o1[i] *= alpha;
            Ps[rbase + i][c0] = p0;
            Ps[rbase + i][c1] = p1;
        }
        __syncwarp();

        // ---- O += P V ----
#pragma unroll 4
        for (int c = 0; c < KT; c += 4) {
            float4 p[4];
#pragma unroll
            for (int i = 0; i < 4; i++) p[i] = *(const float4*)&Ps[rbase + i][c];
#pragma unroll
            for (int j = 0; j < 4; j++) {
                float vv0 = Vs[c + j][lane];
                float vv1 = Vs[c + j][lane + 32];
#pragma unroll
                for (int i = 0; i < 4; i++) {
                    float pj = (&p[i].x)[j];
                    o0[i] += pj * vv0;
                    o1[i] += pj * vv1;
                }
            }
        }
    }

    // ---- epilogue: normalize, write [B,S,D] ----
    float* Og = O + bOff + (long)q0 * D + h * DH;
#pragma unroll
    for (int i = 0; i < 4; i++) {
        float inv = 1.0f / l[i];
        Og[(long)(rbase + i) * D + lane]      = o0[i] * inv;
        Og[(long)(rbase + i) * D + lane + 32] = o1[i] * inv;
    }
}

// ---------------------------------------------------------------------------
// Host entry
// ---------------------------------------------------------------------------
extern "C" void kernel_launch(void* const* d_in, const int* in_sizes, int n_in,
                              void* d_out, int out_size)
{
    const float* x    = (const float*)d_in[0];
    const float* cw   = (const float*)d_in[1];
    const int*   ci   = (const int*)  d_in[2];
    const float* wq   = (const float*)d_in[3];
    const int*   iq   = (const int*)  d_in[4];
    const float* wk   = (const float*)d_in[5];
    const int*   ik   = (const int*)  d_in[6];
    const float* wv   = (const float*)d_in[7];
    const int*   iv   = (const int*)  d_in[8];
    const float* cn   = (const float*)d_in[9];
    const float* pool = (const float*)d_in[10];
    const float* WO   = (const float*)d_in[11];
    float* out = (float*)d_out;

    float* base = nullptr;
    cudaGetSymbolAddress((void**)&base, g_scratch);

    float* Wc  = base;
    float* hB  = Wc  + N_WC;
    float* Wq_ = hB  + N_H;
    float* Wk_ = Wq_ + N_WX;
    float* Wv_ = Wk_ + N_WX;
    float* Qb  = Wv_ + N_WX;
    float* Kb  = Qb  + N_QKV;
    float* Vb  = Kb  + N_QKV;
    float* AO  = Vb  + N_QKV;

    // 1) compress combine
    combine_compress_kernel<<<B * D, 128>>>(cw, ci, cn, Wc);

    // 2) expand combines (Q/K/V weights)
    combine_expand_kernel<<<dim3(B * R, 3), 256>>>(wq, iq, wk, ik, wv, iv, pool,
                                                   Wq_, Wk_, Wv_);

    // 3) h = x @ Wc : per-batch [S,D]@[D,R]
    {
        dim3 grid(R / 64, S / 128, B);
        sgemm_kernel<false><<<grid, 256>>>(x, Wc, hB,
                                           S, R, D, D, R, R,
                                           (long)S * D, (long)D * R, (long)S * R);
    }

    // 4) Q/K/V = h @ W{q,k,v} : per-batch [S,R]@[R,D]
    {
        dim3 grid(D / 64, S / 128, B);
        sgemm_kernel<false><<<grid, 256>>>(hB, Wq_, Qb,
                                           S, D, R, R, D, D,
                                           (long)S * R, (long)R * D, (long)S * D);
        sgemm_kernel<false><<<grid, 256>>>(hB, Wk_, Kb,
                                           S, D, R, R, D, D,
                                           (long)S * R, (long)R * D, (long)S * D);
        sgemm_kernel<false><<<grid, 256>>>(hB, Wv_, Vb,
                                           S, D, R, R, D, D,
                                           (long)S * R, (long)R * D, (long)S * D);
    }

    // 5) causal flash attention
    flash_attn_kernel<<<dim3(S / 32, H, B), 256>>>(Qb, Kb, Vb, AO);

    // 6) out = AO @ W_O^T : [B*S, D] @ [D, D]^T
    {
        dim3 grid(D / 64, (B * S) / 128, 1);
        sgemm_kernel<true><<<grid, 256>>>(AO, WO, out,
                                          B * S, D, D, D, D, D,
                                          0, 0, 0);
    }
}

// round 5
// speedup vs baseline: 1.0148x; 1.0148x over previous
#include <cuda_runtime.h>
#include <cstdint>

// ---------------------------------------------------------------------------
// Problem constants
// ---------------------------------------------------------------------------
static constexpr int B   = 8;
static constexpr int S   = 1024;
static constexpr int D   = 1024;
static constexpr int H   = 16;
static constexpr int DH  = 64;
static constexpr int R   = 128;   // RANK
static constexpr int KC  = 16;
static constexpr int KE  = 8;

// ---------------------------------------------------------------------------
// Scratch layout (floats)
// ---------------------------------------------------------------------------
static constexpr size_t N_WC  = (size_t)B * D * R;
static constexpr size_t N_H   = (size_t)B * S * R;
static constexpr size_t N_WX  = (size_t)B * R * D;
static constexpr size_t N_QKV = (size_t)B * S * D;
static constexpr size_t SCRATCH_FLOATS =
    2 * N_WC + N_H + 6 * N_WX + 4 * N_QKV;

__device__ __align__(1024) float g_scratch[SCRATCH_FLOATS];

// ---------------------------------------------------------------------------
// Helpers
// ---------------------------------------------------------------------------
__device__ __forceinline__ uint32_t smem_u32(const void* p) {
    uint32_t a;
    asm("{ .reg .u64 t; cvta.to.shared.u64 t, %1; cvt.u32.u64 %0, t; }" : "=r"(a) : "l"(p));
    return a;
}
__device__ __forceinline__ float tf32r(float f) {   // round-to-nearest tf32
    uint32_t o;
    asm("cvt.rna.tf32.f32 %0, %1;" : "=r"(o) : "f"(f));
    return __uint_as_float(o);
}
// split fp32 -> (hi, lo) tf32 pair
__device__ __forceinline__ void tf32_split(float v, uint32_t& hi, uint32_t& lo) {
    float h = tf32r(v);
    hi = __float_as_uint(h);
    lo = __float_as_uint(tf32r(v - h));
}

// ---------------------------------------------------------------------------
// Kernel 1: Wc[b,d,r] = sum_k w[b,k] * compress_neurons[idx[b,k]][d][r]
// ---------------------------------------------------------------------------
__global__ void combine_compress_kernel(const float* __restrict__ w,
                                        const int*   __restrict__ idx,
                                        const float* __restrict__ cn,
                                        float*       __restrict__ Wc)
{
    int b = blockIdx.x >> 10;
    int d = blockIdx.x & 1023;
    int r = threadIdx.x;

    __shared__ float sw[KC];
    __shared__ int   si[KC];
    if (r < KC) { sw[r] = w[b * KC + r]; si[r] = idx[b * KC + r]; }
    __syncthreads();

    float acc = 0.f;
#pragma unroll
    for (int k = 0; k < KC; k++)
        acc += sw[k] * cn[((long)si[k] * D + d) * R + r];

    Wc[((long)b * D + d) * R + r] = acc;
}

// ---------------------------------------------------------------------------
// Kernel 2: Wx[b,r,d] = sum_k w[b,k] * expand_pool[idx[b,k]][r][d]
// ---------------------------------------------------------------------------
__global__ void combine_expand_kernel(const float* __restrict__ wq, const int* __restrict__ iq,
                                      const float* __restrict__ wk, const int* __restrict__ ik,
                                      const float* __restrict__ wv, const int* __restrict__ iv,
                                      const float* __restrict__ pool,
                                      float* __restrict__ Wq, float* __restrict__ Wk,
                                      float* __restrict__ Wv)
{
    int mat = blockIdx.y;
    int br  = blockIdx.x;
    int b   = br >> 7;
    int r   = br & 127;

    const float* w   = (mat == 0) ? wq : (mat == 1) ? wk : wv;
    const int*   id  = (mat == 0) ? iq : (mat == 1) ? ik : iv;
    float*       out = (mat == 0) ? Wq : (mat == 1) ? Wk : Wv;

    __shared__ float sw[KE];
    __shared__ int   si[KE];
    int tid = threadIdx.x;
    if (tid < KE) { sw[tid] = w[b * KE + tid]; si[tid] = id[b * KE + tid]; }
    __syncthreads();

    int d0 = tid * 4;
    float4 acc = make_float4(0.f, 0.f, 0.f, 0.f);
#pragma unroll
    for (int k = 0; k < KE; k++) {
        float4 v = *(const float4*)&pool[((long)si[k] * R + r) * D + d0];
        float ww = sw[k];
        acc.x += ww * v.x; acc.y += ww * v.y;
        acc.z += ww * v.z; acc.w += ww * v.w;
    }
    *(float4*)&out[((long)b * R + r) * D + d0] = acc;
}

// ---------------------------------------------------------------------------
// Transpose [X][Y] -> [Y][X] per batch z (full fp32, NO rounding).
// ---------------------------------------------------------------------------
__global__ void transpose_kernel(const float* __restrict__ in,
                                 float* __restrict__ out, int X, int Y)
{
    __shared__ float t[32][33];
    long off = (long)blockIdx.z * X * Y;
    in += off; out += off;
    int x0 = blockIdx.y * 32, y0 = blockIdx.x * 32;
    int tx = threadIdx.x, ty = threadIdx.y;
#pragma unroll
    for (int i = 0; i < 32; i += 8)
        t[ty + i][tx] = in[(long)(x0 + ty + i) * Y + y0 + tx];
    __syncthreads();
#pragma unroll
    for (int i = 0; i < 32; i += 8)
        out[(long)(y0 + ty + i) * X + x0 + tx] = t[tx][ty + i];
}

// ---------------------------------------------------------------------------
// 3xTF32 tensor-core GEMM (near-fp32 accuracy):
//   C[M,N] = A[M,K] @ B[N,K]^T, A/B K-major fp32, fp32 accumulate.
// Each operand split into (hi, lo) tf32 in registers; products
// hi*hi + hi*lo + lo*hi accumulated on the tensor pipe.
// BM=BN=128, BK=32, 256 threads (8 warps: 2M x 4N, warp tile 64x32).
// Double-buffered cp.async, smem tiles [128][36].
// grid (N/128, M/128, batches)
// ---------------------------------------------------------------------------
static constexpr int TILE_F    = 128 * 36;
static constexpr int GEMM_SMEM = 4 * TILE_F * 4;   // 73728 B

#define MMA_TF32(ACC, AR, B0, B1)                                              \
    asm volatile("mma.sync.aligned.m16n8k8.row.col.f32.tf32.tf32.f32 "         \
        "{%0,%1,%2,%3}, {%4,%5,%6,%7}, {%8,%9}, {%0,%1,%2,%3};"                \
        : "+f"((ACC)[0]), "+f"((ACC)[1]), "+f"((ACC)[2]), "+f"((ACC)[3])       \
        : "r"((AR)[0]), "r"((AR)[1]), "r"((AR)[2]), "r"((AR)[3]),              \
          "r"(B0), "r"(B1))

__global__ void __launch_bounds__(256)
mma_gemm(const float* __restrict__ A, const float* __restrict__ Bm,
         float* __restrict__ C,
         int K, int lda, int ldb, int ldc, long sA, long sB, long sC)
{
    extern __shared__ float smem[];
    int tid = threadIdx.x, wid = tid >> 5, lane = tid & 31;
    int wm = wid & 1, wn = wid >> 1;         // warp coords: 2 x 4
    int qr = lane >> 2, qc = lane & 3;       // quad row/col

    A  += (long)blockIdx.z * sA;
    Bm += (long)blockIdx.z * sB;
    C  += (long)blockIdx.z * sC;
    int m0 = blockIdx.y * 128, n0 = blockIdx.x * 128;

    float* AS[2] = { smem,              smem + TILE_F };
    float* BS[2] = { smem + 2 * TILE_F, smem + 3 * TILE_F };

    float acc[4][4][4];
#pragma unroll
    for (int mi = 0; mi < 4; mi++)
#pragma unroll
        for (int ni = 0; ni < 4; ni++)
#pragma unroll
            for (int c = 0; c < 4; c++) acc[mi][ni][c] = 0.f;

    int nt = K / 32;

    auto load_stage = [&](int kt, int st) {
        const float* Ak = A + kt * 32;
        const float* Bk = Bm + kt * 32;
#pragma unroll
        for (int i = 0; i < 4; i++) {
            int g = tid + i * 256;
            int row = g >> 3, f4 = (g & 7) * 4;
            uint32_t da = smem_u32(&AS[st][row * 36 + f4]);
            const float* ga = Ak + (long)(m0 + row) * lda + f4;
            asm volatile("cp.async.cg.shared.global [%0], [%1], 16;" :: "r"(da), "l"(ga));
            uint32_t db = smem_u32(&BS[st][row * 36 + f4]);
            const float* gb = Bk + (long)(n0 + row) * ldb + f4;
            asm volatile("cp.async.cg.shared.global [%0], [%1], 16;" :: "r"(db), "l"(gb));
        }
        asm volatile("cp.async.commit_group;" ::: "memory");
    };

    load_stage(0, 0);

    for (int kt = 0; kt < nt; kt++) {
        if (kt + 1 < nt) {
            load_stage(kt + 1, (kt + 1) & 1);
            asm volatile("cp.async.wait_group 1;" ::: "memory");
        } else {
            asm volatile("cp.async.wait_group 0;" ::: "memory");
        }
        __syncthreads();

        const float* As = AS[kt & 1];
        const float* Bs = BS[kt & 1];
#pragma unroll
        for (int ks = 0; ks < 4; ks++) {
            uint32_t ahi[4][4], alo[4][4];
#pragma unroll
            for (int mi = 0; mi < 4; mi++) {
                const float* ap = As + (wm * 64 + mi * 16 + qr) * 36 + ks * 8 + qc;
                tf32_split(ap[0],           ahi[mi][0], alo[mi][0]);
                tf32_split(ap[8 * 36],      ahi[mi][1], alo[mi][1]);
                tf32_split(ap[4],           ahi[mi][2], alo[mi][2]);
                tf32_split(ap[8 * 36 + 4],  ahi[mi][3], alo[mi][3]);
            }
            uint32_t bhi[4][2], blo[4][2];
#pragma unroll
            for (int ni = 0; ni < 4; ni++) {
                const float* bp = Bs + (wn * 32 + ni * 8 + qr) * 36 + ks * 8 + qc;
                tf32_split(bp[0], bhi[ni][0], blo[ni][0]);
                tf32_split(bp[4], bhi[ni][1], blo[ni][1]);
            }
#pragma unroll
            for (int mi = 0; mi < 4; mi++)
#pragma unroll
                for (int ni = 0; ni < 4; ni++) {
                    MMA_TF32(acc[mi][ni], alo[mi], bhi[ni][0], bhi[ni][1]);  // lo*hi
                    MMA_TF32(acc[mi][ni], ahi[mi], blo[ni][0], blo[ni][1]);  // hi*lo
                    MMA_TF32(acc[mi][ni], ahi[mi], bhi[ni][0], bhi[ni][1]);  // hi*hi
                }
        }
        __syncthreads();
    }

    // ---- epilogue ----
#pragma unroll
    for (int mi = 0; mi < 4; mi++) {
        int row = m0 + wm * 64 + mi * 16 + qr;
#pragma unroll
        for (int ni = 0; ni < 4; ni++) {
            int col = n0 + wn * 32 + ni * 8 + qc * 2;
            *(float2*)&C[(long)row * ldc + col] =
                make_float2(acc[mi][ni][0], acc[mi][ni][1]);
            *(float2*)&C[(long)(row + 8) * ldc + col] =
                make_float2(acc[mi][ni][2], acc[mi][ni][3]);
        }
    }
}

// ---------------------------------------------------------------------------
// Causal flash attention, fp32.
// ---------------------------------------------------------------------------
__global__ void __launch_bounds__(256)
flash_attn_kernel(const float* __restrict__ Q, const float* __restrict__ K,
                  const float* __restrict__ V, float* __restrict__ O)
{
    constexpr int QT = 32, KT = 64;

    __shared__ float4 Qs [QT][DH / 4];
    __shared__ float4 Ksw[KT][DH / 4];
    __shared__ float  Vs [KT][DH];
    __shared__ float  Ps [QT][KT];

    int qt = blockIdx.x, h = blockIdx.y, b = blockIdx.z;
    int q0 = qt * QT;
    int tid = threadIdx.x, warp = tid >> 5, lane = tid & 31;

    const long bOff = (long)b * S * D;
    const float* Qg = Q + bOff + (long)q0 * D + h * DH;
    const float* Kg = K + bOff + h * DH;
    const float* Vg = V + bOff + h * DH;

    for (int i = tid; i < QT * (DH / 4); i += 256) {
        int r = i >> 4, d4 = i & 15;
        Qs[r][d4] = *(const float4*)&Qg[(long)r * D + d4 * 4];
    }

    float m[4], l[4], o0[4], o1[4];
#pragma unroll
    for (int i = 0; i < 4; i++) { m[i] = -1e30f; l[i] = 0.f; o0[i] = 0.f; o1[i] = 0.f; }

    int rbase = warp * 4;
    int nkt = q0 / KT + 1;
    const float scale = 0.125f;
    int c0 = lane, c1 = lane + 32;
    int swz = lane & 7;

    for (int kt = 0; kt < nkt; kt++) {
        __syncthreads();
        for (int i = tid; i < KT * (DH / 4); i += 256) {
            int c = i >> 4, d4 = i & 15;
            long gro = (long)(kt * KT + c) * D + d4 * 4;
            Ksw[c][d4 ^ (c & 7)] = *(const float4*)&Kg[gro];
            *(float4*)&Vs[c][d4 * 4] = *(const float4*)&Vg[gro];
        }
        __syncthreads();

        float s0[4], s1[4];
#pragma unroll
        for (int i = 0; i < 4; i++) { s0[i] = 0.f; s1[i] = 0.f; }
#pragma unroll
        for (int d4 = 0; d4 < DH / 4; d4++) {
            float4 k0v = Ksw[c0][d4 ^ swz];
            float4 k1v = Ksw[c1][d4 ^ swz];
#pragma unroll
            for (int i = 0; i < 4; i++) {
                float4 q = Qs[rbase + i][d4];
                s0[i] += q.x * k0v.x + q.y * k0v.y + q.z * k0v.z + q.w * k0v.w;
                s1[i] += q.x * k1v.x + q.y * k1v.y + q.z * k1v.z + q.w * k1v.w;
            }
        }

        bool lastTile = (kt == nkt - 1);
#pragma unroll
        for (int i = 0; i < 4; i++) {
            int row = q0 + rbase + i;
            float v0 = s0[i] * scale;
            float v1 = s1[i] * scale;
            if (lastTile) {
                if (kt * KT + c0 > row) v0 = -1e30f;
                if (kt * KT + c1 > row) v1 = -1e30f;
            }
            float mt = fmaxf(v0, v1);
#pragma unroll
            for (int off = 16; off; off >>= 1)
                mt = fmaxf(mt, __shfl_xor_sync(0xffffffffu, mt, off));
            float mnew  = fmaxf(m[i], mt);
            float alpha = __expf(m[i] - mnew);
            float p0 = __expf(v0 - mnew);
            float p1 = __expf(v1 - mnew);
            float rs = p0 + p1;
#pragma unroll
            for (int off = 16; off; off >>= 1)
                rs += __shfl_xor_sync(0xffffffffu, rs, off);
            l[i] = l[i] * alpha + rs;
            m[i] = mnew;
            o0[i] *= alpha;
            o1[i] *= alpha;
            Ps[rbase + i][c0] = p0;
            Ps[rbase + i][c1] = p1;
        }
        __syncwarp();

#pragma unroll 4
        for (int c = 0; c < KT; c += 4) {
            float4 p[4];
#pragma unroll
            for (int i = 0; i < 4; i++) p[i] = *(const float4*)&Ps[rbase + i][c];
#pragma unroll
            for (int j = 0; j < 4; j++) {
                float vv0 = Vs[c + j][lane];
                float vv1 = Vs[c + j][lane + 32];
#pragma unroll
                for (int i = 0; i < 4; i++) {
                    float pj = (&p[i].x)[j];
                    o0[i] += pj * vv0;
                    o1[i] += pj * vv1;
                }
            }
        }
    }

    float* Og = O + bOff + (long)q0 * D + h * DH;
#pragma unroll
    for (int i = 0; i < 4; i++) {
        float inv = 1.0f / l[i];
        Og[(long)(rbase + i) * D + lane]      = o0[i] * inv;
        Og[(long)(rbase + i) * D + lane + 32] = o1[i] * inv;
    }
}

// ---------------------------------------------------------------------------
// Host entry
// ---------------------------------------------------------------------------
extern "C" void kernel_launch(void* const* d_in, const int* in_sizes, int n_in,
                              void* d_out, int out_size)
{
    const float* x    = (const float*)d_in[0];
    const float* cw   = (const float*)d_in[1];
    const int*   ci   = (const int*)  d_in[2];
    const float* wq   = (const float*)d_in[3];
    const int*   iq   = (const int*)  d_in[4];
    const float* wk   = (const float*)d_in[5];
    const int*   ik   = (const int*)  d_in[6];
    const float* wv   = (const float*)d_in[7];
    const int*   iv   = (const int*)  d_in[8];
    const float* cn   = (const float*)d_in[9];
    const float* pool = (const float*)d_in[10];
    const float* WO   = (const float*)d_in[11];
    float* out = (float*)d_out;

    float* base = nullptr;
    cudaGetSymbolAddress((void**)&base, g_scratch);

    float* Wc   = base;
    float* WcT  = Wc   + N_WC;
    float* hB   = WcT  + N_WC;
    float* Wq_  = hB   + N_H;
    float* Wk_  = Wq_  + N_WX;
    float* Wv_  = Wk_  + N_WX;
    float* WqT  = Wv_  + N_WX;            // WqT/WkT/WvT contiguous
    float* Qb   = WqT  + 3 * N_WX;
    float* Kb   = Qb   + N_QKV;
    float* Vb   = Kb   + N_QKV;
    float* AO   = Vb   + N_QKV;

    cudaFuncSetAttribute(mma_gemm,
                         cudaFuncAttributeMaxDynamicSharedMemorySize, GEMM_SMEM);

    // 1) combines
    combine_compress_kernel<<<B * D, 128>>>(cw, ci, cn, Wc);
    combine_expand_kernel<<<dim3(B * R, 3), 256>>>(wq, iq, wk, ik, wv, iv, pool,
                                                   Wq_, Wk_, Wv_);

    // 2) transpose weights into [N][K] K-major (full fp32)
    transpose_kernel<<<dim3(R / 32, D / 32, B), dim3(32, 8)>>>(Wc, WcT, D, R);
    transpose_kernel<<<dim3(D / 32, R / 32, 3 * B), dim3(32, 8)>>>(Wq_, WqT, R, D);

    // 3) h = x @ WcT^T   (M=S, N=R, K=D)
    mma_gemm<<<dim3(R / 128, S / 128, B), 256, GEMM_SMEM>>>(
        x, WcT, hB, D, D, D, R, (long)S * D, (long)R * D, (long)S * R);

    // 4) Q/K/V = h @ WxT^T  (M=S, N=D, K=R)
    mma_gemm<<<dim3(D / 128, S / 128, B), 256, GEMM_SMEM>>>(
        hB, WqT,            Qb, R, R, R, D, (long)S * R, (long)D * R, (long)S * D);
    mma_gemm<<<dim3(D / 128, S / 128, B), 256, GEMM_SMEM>>>(
        hB, WqT + N_WX,     Kb, R, R, R, D, (long)S * R, (long)D * R, (long)S * D);
    mma_gemm<<<dim3(D / 128, S / 128, B), 256, GEMM_SMEM>>>(
        hB, WqT + 2 * N_WX, Vb, R, R, R, D, (long)S * R, (long)D * R, (long)S * D);

    // 5) causal flash attention (fp32)
    flash_attn_kernel<<<dim3(S / 32, H, B), 256>>>(Qb, Kb, Vb, AO);

    // 6) out = AO @ W_O^T  (M=B*S, N=D, K=D) -- W_O naturally [N][K]
    mma_gemm<<<dim3(D / 128, (B * S) / 128, 1), 256, GEMM_SMEM>>>(
        AO, WO, out, D, D, D, D, 0, 0, 0);
}

// round 9
// speedup vs baseline: 1.1991x; 1.1817x over previous
#include <cuda_runtime.h>
#include <cstdint>

// ---------------------------------------------------------------------------
// Problem constants
// ---------------------------------------------------------------------------
static constexpr int B   = 8;
static constexpr int S   = 1024;
static constexpr int D   = 1024;
static constexpr int H   = 16;
static constexpr int DH  = 64;
static constexpr int R   = 128;   // RANK
static constexpr int KC  = 16;
static constexpr int KE  = 8;

// ---------------------------------------------------------------------------
// Scratch layout (floats)
// ---------------------------------------------------------------------------
static constexpr size_t N_WC  = (size_t)B * D * R;
static constexpr size_t N_H   = (size_t)B * S * R;
static constexpr size_t N_WX  = (size_t)B * R * D;
static constexpr size_t N_QKV = (size_t)B * S * D;
static constexpr size_t SCRATCH_FLOATS =
    2 * N_WC + N_H + 6 * N_WX + 4 * N_QKV;

__device__ __align__(1024) float g_scratch[SCRATCH_FLOATS];

// ---------------------------------------------------------------------------
// Helpers
// ---------------------------------------------------------------------------
__device__ __forceinline__ uint32_t smem_u32(const void* p) {
    uint32_t a;
    asm("{ .reg .u64 t; cvta.to.shared.u64 t, %1; cvt.u32.u64 %0, t; }" : "=r"(a) : "l"(p));
    return a;
}
// bf16x2 split: pack (v0,v1) -> hi pair + lo pair (lo = v - bf16(v), RN).
// Register layout: low 16 bits = first k element (v0), high = v1.
__device__ __forceinline__ void bf16x2_split(float v0, float v1,
                                             uint32_t& hi, uint32_t& lo) {
    uint32_t h;
    asm("cvt.rn.bf16x2.f32 %0, %1, %2;" : "=r"(h) : "f"(v1), "f"(v0));
    float h0 = __uint_as_float(h << 16);
    float h1 = __uint_as_float(h & 0xFFFF0000u);
    uint32_t l;
    asm("cvt.rn.bf16x2.f32 %0, %1, %2;" : "=r"(l) : "f"(v1 - h1), "f"(v0 - h0));
    hi = h; lo = l;
}

// ---------------------------------------------------------------------------
// Kernel 1: Wc[b,d,r] = sum_k w[b,k] * compress_neurons[idx[b,k]][d][r]
// ---------------------------------------------------------------------------
__global__ void combine_compress_kernel(const float* __restrict__ w,
                                        const int*   __restrict__ idx,
                                        const float* __restrict__ cn,
                                        float*       __restrict__ Wc)
{
    int b = blockIdx.x >> 10;
    int d = blockIdx.x & 1023;
    int r = threadIdx.x;

    __shared__ float sw[KC];
    __shared__ int   si[KC];
    if (r < KC) { sw[r] = w[b * KC + r]; si[r] = idx[b * KC + r]; }
    __syncthreads();

    float acc = 0.f;
#pragma unroll
    for (int k = 0; k < KC; k++)
        acc += sw[k] * cn[((long)si[k] * D + d) * R + r];

    Wc[((long)b * D + d) * R + r] = acc;
}

// ---------------------------------------------------------------------------
// Kernel 2: Wx[b,r,d] = sum_k w[b,k] * expand_pool[idx[b,k]][r][d]
// ---------------------------------------------------------------------------
__global__ void combine_expand_kernel(const float* __restrict__ wq, const int* __restrict__ iq,
                                      const float* __restrict__ wk, const int* __restrict__ ik,
                                      const float* __restrict__ wv, const int* __restrict__ iv,
                                      const float* __restrict__ pool,
                                      float* __restrict__ Wq, float* __restrict__ Wk,
                                      float* __restrict__ Wv)
{
    int mat = blockIdx.y;
    int br  = blockIdx.x;
    int b   = br >> 7;
    int r   = br & 127;

    const float* w   = (mat == 0) ? wq : (mat == 1) ? wk : wv;
    const int*   id  = (mat == 0) ? iq : (mat == 1) ? ik : iv;
    float*       out = (mat == 0) ? Wq : (mat == 1) ? Wk : Wv;

    __shared__ float sw[KE];
    __shared__ int   si[KE];
    int tid = threadIdx.x;
    if (tid < KE) { sw[tid] = w[b * KE + tid]; si[tid] = id[b * KE + tid]; }
    __syncthreads();

    int d0 = tid * 4;
    float4 acc = make_float4(0.f, 0.f, 0.f, 0.f);
#pragma unroll
    for (int k = 0; k < KE; k++) {
        float4 v = *(const float4*)&pool[((long)si[k] * R + r) * D + d0];
        float ww = sw[k];
        acc.x += ww * v.x; acc.y += ww * v.y;
        acc.z += ww * v.z; acc.w += ww * v.w;
    }
    *(float4*)&out[((long)b * R + r) * D + d0] = acc;
}

// ---------------------------------------------------------------------------
// Transpose [X][Y] -> [Y][X] per batch z (full fp32).
// ---------------------------------------------------------------------------
__global__ void transpose_kernel(const float* __restrict__ in,
                                 float* __restrict__ out, int X, int Y)
{
    __shared__ float t[32][33];
    long off = (long)blockIdx.z * X * Y;
    in += off; out += off;
    int x0 = blockIdx.y * 32, y0 = blockIdx.x * 32;
    int tx = threadIdx.x, ty = threadIdx.y;
#pragma unroll
    for (int i = 0; i < 32; i += 8)
        t[ty + i][tx] = in[(long)(x0 + ty + i) * Y + y0 + tx];
    __syncthreads();
#pragma unroll
    for (int i = 0; i < 32; i += 8)
        out[(long)(y0 + ty + i) * X + x0 + tx] = t[tx][ty + i];
}

// ---------------------------------------------------------------------------
// bf16x2 (3-product) tensor-core GEMM, near-fp32 accuracy:
//   C[M,N] = A[M,K] @ B[N,K]^T, A/B K-major fp32, fp32 accumulate.
// Operands split in-register into bf16 (hi, lo); products hh + hl + lh
// accumulated via mma.sync.m16n8k16.bf16 (ll term ~2^-18, dropped).
// BM=BN=128, BK=32, 256 threads (8 warps: 2M x 4N, warp tile 64x32).
// Double-buffered cp.async, smem tiles [128][36].
// grid (N/128, M/128, batches)
// ---------------------------------------------------------------------------
static constexpr int TILE_F    = 128 * 36;
static constexpr int GEMM_SMEM = 4 * TILE_F * 4;   // 73728 B

#define MMA_BF16(ACC, A0, A1, A2, A3, B0, B1)                                  \
    asm volatile("mma.sync.aligned.m16n8k16.row.col.f32.bf16.bf16.f32 "        \
        "{%0,%1,%2,%3}, {%4,%5,%6,%7}, {%8,%9}, {%0,%1,%2,%3};"                \
        : "+f"((ACC)[0]), "+f"((ACC)[1]), "+f"((ACC)[2]), "+f"((ACC)[3])       \
        : "r"(A0), "r"(A1), "r"(A2), "r"(A3), "r"(B0), "r"(B1))

__global__ void __launch_bounds__(256)
mma_gemm(const float* __restrict__ A, const float* __restrict__ Bm,
         float* __restrict__ C,
         int K, int lda, int ldb, int ldc, long sA, long sB, long sC)
{
    extern __shared__ float smem[];
    int tid = threadIdx.x, wid = tid >> 5, lane = tid & 31;
    int wm = wid & 1, wn = wid >> 1;         // warp coords: 2 x 4
    int qr = lane >> 2, qc = lane & 3;       // quad row/col

    A  += (long)blockIdx.z * sA;
    Bm += (long)blockIdx.z * sB;
    C  += (long)blockIdx.z * sC;
    int m0 = blockIdx.y * 128, n0 = blockIdx.x * 128;

    float* AS[2] = { smem,              smem + TILE_F };
    float* BS[2] = { smem + 2 * TILE_F, smem + 3 * TILE_F };

    float acc[4][4][4];
#pragma unroll
    for (int mi = 0; mi < 4; mi++)
#pragma unroll
        for (int ni = 0; ni < 4; ni++)
#pragma unroll
            for (int c = 0; c < 4; c++) acc[mi][ni][c] = 0.f;

    int nt = K / 32;

    auto load_stage = [&](int kt, int st) {
        const float* Ak = A + kt * 32;
        const float* Bk = Bm + kt * 32;
#pragma unroll
        for (int i = 0; i < 4; i++) {
            int g = tid + i * 256;
            int row = g >> 3, f4 = (g & 7) * 4;
            uint32_t da = smem_u32(&AS[st][row * 36 + f4]);
            const float* ga = Ak + (long)(m0 + row) * lda + f4;
            asm volatile("cp.async.cg.shared.global [%0], [%1], 16;" :: "r"(da), "l"(ga));
            uint32_t db = smem_u32(&BS[st][row * 36 + f4]);
            const float* gb = Bk + (long)(n0 + row) * ldb + f4;
            asm volatile("cp.async.cg.shared.global [%0], [%1], 16;" :: "r"(db), "l"(gb));
        }
        asm volatile("cp.async.commit_group;" ::: "memory");
    };

    load_stage(0, 0);

    for (int kt = 0; kt < nt; kt++) {
        if (kt + 1 < nt) {
            load_stage(kt + 1, (kt + 1) & 1);
            asm volatile("cp.async.wait_group 1;" ::: "memory");
        } else {
            asm volatile("cp.async.wait_group 0;" ::: "memory");
        }
        __syncthreads();

        const float* As = AS[kt & 1];
        const float* Bs = BS[kt & 1];
#pragma unroll
        for (int ks = 0; ks < 2; ks++) {          // two k16 steps per BK=32
            uint32_t ahi[4][4], alo[4][4];
#pragma unroll
            for (int mi = 0; mi < 4; mi++) {
                const float* ap = As + (wm * 64 + mi * 16 + qr) * 36 + ks * 16 + qc * 2;
                float2 v;
                v = *(const float2*)(ap);                 // row qr,  k lo
                bf16x2_split(v.x, v.y, ahi[mi][0], alo[mi][0]);
                v = *(const float2*)(ap + 8 * 36);        // row qr+8, k lo
                bf16x2_split(v.x, v.y, ahi[mi][1], alo[mi][1]);
                v = *(const float2*)(ap + 8);             // row qr,  k hi
                bf16x2_split(v.x, v.y, ahi[mi][2], alo[mi][2]);
                v = *(const float2*)(ap + 8 * 36 + 8);    // row qr+8, k hi
                bf16x2_split(v.x, v.y, ahi[mi][3], alo[mi][3]);
            }
            uint32_t bhi[4][2], blo[4][2];
#pragma unroll
            for (int ni = 0; ni < 4; ni++) {
                const float* bp = Bs + (wn * 32 + ni * 8 + qr) * 36 + ks * 16 + qc * 2;
                float2 v;
                v = *(const float2*)(bp);                 // col qr, k lo
                bf16x2_split(v.x, v.y, bhi[ni][0], blo[ni][0]);
                v = *(const float2*)(bp + 8);             // col qr, k hi
                bf16x2_split(v.x, v.y, bhi[ni][1], blo[ni][1]);
            }
#pragma unroll
            for (int mi = 0; mi < 4; mi++)
#pragma unroll
                for (int ni = 0; ni < 4; ni++) {
                    MMA_BF16(acc[mi][ni], alo[mi][0], alo[mi][1], alo[mi][2], alo[mi][3],
                             bhi[ni][0], bhi[ni][1]);                          // lo*hi
                    MMA_BF16(acc[mi][ni], ahi[mi][0], ahi[mi][1], ahi[mi][2], ahi[mi][3],
                             blo[ni][0], blo[ni][1]);                          // hi*lo
                    MMA_BF16(acc[mi][ni], ahi[mi][0], ahi[mi][1], ahi[mi][2], ahi[mi][3],
                             bhi[ni][0], bhi[ni][1]);                          // hi*hi
                }
        }
        __syncthreads();
    }

    // ---- epilogue ----
#pragma unroll
    for (int mi = 0; mi < 4; mi++) {
        int row = m0 + wm * 64 + mi * 16 + qr;
#pragma unroll
        for (int ni = 0; ni < 4; ni++) {
            int col = n0 + wn * 32 + ni * 8 + qc * 2;
            *(float2*)&C[(long)row * ldc + col] =
                make_float2(acc[mi][ni][0], acc[mi][ni][1]);
            *(float2*)&C[(long)(row + 8) * ldc + col] =
                make_float2(acc[mi][ni][2], acc[mi][ni][3]);
        }
    }
}

// ---------------------------------------------------------------------------
// Causal flash attention, fp32.
// ---------------------------------------------------------------------------
__global__ void __launch_bounds__(256)
flash_attn_kernel(const float* __restrict__ Q, const float* __restrict__ K,
                  const float* __restrict__ V, float* __restrict__ O)
{
    constexpr int QT = 32, KT = 64;

    __shared__ float4 Qs [QT][DH / 4];
    __shared__ float4 Ksw[KT][DH / 4];
    __shared__ float  Vs [KT][DH];
    __shared__ float  Ps [QT][KT];

    int qt = blockIdx.x, h = blockIdx.y, b = blockIdx.z;
    int q0 = qt * QT;
    int tid = threadIdx.x, warp = tid >> 5, lane = tid & 31;

    const long bOff = (long)b * S * D;
    const float* Qg = Q + bOff + (long)q0 * D + h * DH;
    const float* Kg = K + bOff + h * DH;
    const float* Vg = V + bOff + h * DH;

    for (int i = tid; i < QT * (DH / 4); i += 256) {
        int r = i >> 4, d4 = i & 15;
        Qs[r][d4] = *(const float4*)&Qg[(long)r * D + d4 * 4];
    }

    float m[4], l[4], o0[4], o1[4];
#pragma unroll
    for (int i = 0; i < 4; i++) { m[i] = -1e30f; l[i] = 0.f; o0[i] = 0.f; o1[i] = 0.f; }

    int rbase = warp * 4;
    int nkt = q0 / KT + 1;
    const float scale = 0.125f;
    int c0 = lane, c1 = lane + 32;
    int swz = lane & 7;

    for (int kt = 0; kt < nkt; kt++) {
        __syncthreads();
        for (int i = tid; i < KT * (DH / 4); i += 256) {
            int c = i >> 4, d4 = i & 15;
            long gro = (long)(kt * KT + c) * D + d4 * 4;
            Ksw[c][d4 ^ (c & 7)] = *(const float4*)&Kg[gro];
            *(float4*)&Vs[c][d4 * 4] = *(const float4*)&Vg[gro];
        }
        __syncthreads();

        float s0[4], s1[4];
#pragma unroll
        for (int i = 0; i < 4; i++) { s0[i] = 0.f; s1[i] = 0.f; }
#pragma unroll
        for (int d4 = 0; d4 < DH / 4; d4++) {
            float4 k0v = Ksw[c0][d4 ^ swz];
            float4 k1v = Ksw[c1][d4 ^ swz];
#pragma unroll
            for (int i = 0; i < 4; i++) {
                float4 q = Qs[rbase + i][d4];
                s0[i] += q.x * k0v.x + q.y * k0v.y + q.z * k0v.z + q.w * k0v.w;
                s1[i] += q.x * k1v.x + q.y * k1v.y + q.z * k1v.z + q.w * k1v.w;
            }
        }

        bool lastTile = (kt == nkt - 1);
#pragma unroll
        for (int i = 0; i < 4; i++) {
            int row = q0 + rbase + i;
            float v0 = s0[i] * scale;
            float v1 = s1[i] * scale;
            if (lastTile) {
                if (kt * KT + c0 > row) v0 = -1e30f;
                if (kt * KT + c1 > row) v1 = -1e30f;
            }
            float mt = fmaxf(v0, v1);
#pragma unroll
            for (int off = 16; off; off >>= 1)
                mt = fmaxf(mt, __shfl_xor_sync(0xffffffffu, mt, off));
            float mnew  = fmaxf(m[i], mt);
            float alpha = __expf(m[i] - mnew);
            float p0 = __expf(v0 - mnew);
            float p1 = __expf(v1 - mnew);
            float rs = p0 + p1;
#pragma unroll
            for (int off = 16; off; off >>= 1)
                rs += __shfl_xor_sync(0xffffffffu, rs, off);
            l[i] = l[i] * alpha + rs;
            m[i] = mnew;
            o0[i] *= alpha;
            o1[i] *= alpha;
            Ps[rbase + i][c0] = p0;
            Ps[rbase + i][c1] = p1;
        }
        __syncwarp();

#pragma unroll 4
        for (int c = 0; c < KT; c += 4) {
            float4 p[4];
#pragma unroll
            for (int i = 0; i < 4; i++) p[i] = *(const float4*)&Ps[rbase + i][c];
#pragma unroll
            for (int j = 0; j < 4; j++) {
                float vv0 = Vs[c + j][lane];
                float vv1 = Vs[c + j][lane + 32];
#pragma unroll
                for (int i = 0; i < 4; i++) {
                    float pj = (&p[i].x)[j];
                    o0[i] += pj * vv0;
                    o1[i] += pj * vv1;
                }
            }
        }
    }

    float* Og = O + bOff + (long)q0 * D + h * DH;
#pragma unroll
    for (int i = 0; i < 4; i++) {
        float inv = 1.0f / l[i];
        Og[(long)(rbase + i) * D + lane]      = o0[i] * inv;
        Og[(long)(rbase + i) * D + lane + 32] = o1[i] * inv;
    }
}

// ---------------------------------------------------------------------------
// Host entry
// ---------------------------------------------------------------------------
extern "C" void kernel_launch(void* const* d_in, const int* in_sizes, int n_in,
                              void* d_out, int out_size)
{
    const float* x    = (const float*)d_in[0];
    const float* cw   = (const float*)d_in[1];
    const int*   ci   = (const int*)  d_in[2];
    const float* wq   = (const float*)d_in[3];
    const int*   iq   = (const int*)  d_in[4];
    const float* wk   = (const float*)d_in[5];
    const int*   ik   = (const int*)  d_in[6];
    const float* wv   = (const float*)d_in[7];
    const int*   iv   = (const int*)  d_in[8];
    const float* cn   = (const float*)d_in[9];
    const float* pool = (const float*)d_in[10];
    const float* WO   = (const float*)d_in[11];
    float* out = (float*)d_out;

    float* base = nullptr;
    cudaGetSymbolAddress((void**)&base, g_scratch);

    float* Wc   = base;
    float* WcT  = Wc   + N_WC;
    float* hB   = WcT  + N_WC;
    float* Wq_  = hB   + N_H;
    float* Wk_  = Wq_  + N_WX;
    float* Wv_  = Wk_  + N_WX;
    float* WqT  = Wv_  + N_WX;            // WqT/WkT/WvT contiguous
    float* Qb   = WqT  + 3 * N_WX;
    float* Kb   = Qb   + N_QKV;
    float* Vb   = Kb   + N_QKV;
    float* AO   = Vb   + N_QKV;

    cudaFuncSetAttribute(mma_gemm,
                         cudaFuncAttributeMaxDynamicSharedMemorySize, GEMM_SMEM);

    // 1) combines
    combine_compress_kernel<<<B * D, 128>>>(cw, ci, cn, Wc);
    combine_expand_kernel<<<dim3(B * R, 3), 256>>>(wq, iq, wk, ik, wv, iv, pool,
                                                   Wq_, Wk_, Wv_);

    // 2) transpose weights into [N][K] K-major (full fp32)
    transpose_kernel<<<dim3(R / 32, D / 32, B), dim3(32, 8)>>>(Wc, WcT, D, R);
    transpose_kernel<<<dim3(D / 32, R / 32, 3 * B), dim3(32, 8)>>>(Wq_, WqT, R, D);

    // 3) h = x @ WcT^T   (M=S, N=R, K=D)
    mma_gemm<<<dim3(R / 128, S / 128, B), 256, GEMM_SMEM>>>(
        x, WcT, hB, D, D, D, R, (long)S * D, (long)R * D, (long)S * R);

    // 4) Q/K/V = h @ WxT^T  (M=S, N=D, K=R)
    mma_gemm<<<dim3(D / 128, S / 128, B), 256, GEMM_SMEM>>>(
        hB, WqT,            Qb, R, R, R, D, (long)S * R, (long)D * R, (long)S * D);
    mma_gemm<<<dim3(D / 128, S / 128, B), 256, GEMM_SMEM>>>(
        hB, WqT + N_WX,     Kb, R, R, R, D, (long)S * R, (long)D * R, (long)S * D);
    mma_gemm<<<dim3(D / 128, S / 128, B), 256, GEMM_SMEM>>>(
        hB, WqT + 2 * N_WX, Vb, R, R, R, D, (long)S * R, (long)D * R, (long)S * D);

    // 5) causal flash attention (fp32)
    flash_attn_kernel<<<dim3(S / 32, H, B), 256>>>(Qb, Kb, Vb, AO);

    // 6) out = AO @ W_O^T  (M=B*S, N=D, K=D) -- W_O naturally [N][K]
    mma_gemm<<<dim3(D / 128, (B * S) / 128, 1), 256, GEMM_SMEM>>>(
        AO, WO, out, D, D, D, D, 0, 0, 0);
}

// round 11
// speedup vs baseline: 2.4268x; 2.0238x over previous
#include <cuda_runtime.h>
#include <cuda_fp16.h>
#include <cstdint>

// ---------------------------------------------------------------------------
// Problem constants
// ---------------------------------------------------------------------------
static constexpr int B   = 8;
static constexpr int S   = 1024;
static constexpr int D   = 1024;
static constexpr int H   = 16;
static constexpr int DH  = 64;
static constexpr int R   = 128;   // RANK
static constexpr int KC  = 16;
static constexpr int KE  = 8;

// ---------------------------------------------------------------------------
// Scratch layout
// ---------------------------------------------------------------------------
static constexpr size_t N_WC  = (size_t)B * D * R;
static constexpr size_t N_H   = (size_t)B * S * R;
static constexpr size_t N_WX  = (size_t)B * R * D;
static constexpr size_t N_QKV = (size_t)B * S * D;
static constexpr size_t N_WO  = (size_t)D * D;
// halves: x(2) WcT(2) WqkvT(6 NWX) h(2 NH) QKV(6) AO(2) WO(2)
static constexpr size_t HALVES =
    10 * N_QKV + 2 * N_WC + 6 * N_WX + 2 * N_H + 2 * N_WO;
static constexpr size_t SCRATCH_FLOATS = N_WC + 3 * N_WX + (HALVES + 1) / 2;

__device__ __align__(1024) float g_scratch[SCRATCH_FLOATS];

// ---------------------------------------------------------------------------
// Helpers
// ---------------------------------------------------------------------------
// split pair (a=even/low, b=odd/high) -> packed fp16x2 hi + fp16x2 lo
__device__ __forceinline__ void split2(float a, float b, uint32_t& hi, uint32_t& lo) {
    __half2 h = __floats2half2_rn(a, b);           // h.x=a (low 16), h.y=b
    hi = *reinterpret_cast<uint32_t*>(&h);
    float2 f = __half22float2(h);
    __half2 l = __floats2half2_rn(a - f.x, b - f.y);
    lo = *reinterpret_cast<uint32_t*>(&l);
}

#define MMA_F16(ACC, A0, A1, A2, A3, B0, B1)                                   \
    asm volatile("mma.sync.aligned.m16n8k16.row.col.f32.f16.f16.f32 "          \
        "{%0,%1,%2,%3}, {%4,%5,%6,%7}, {%8,%9}, {%0,%1,%2,%3};"                \
        : "+f"((ACC)[0]), "+f"((ACC)[1]), "+f"((ACC)[2]), "+f"((ACC)[3])       \
        : "r"(A0), "r"(A1), "r"(A2), "r"(A3), "r"(B0), "r"(B1))

#define CP16(dst_half_ptr, src_ptr)                                            \
    asm volatile("cp.async.cg.shared.global [%0], [%1], 16;"                   \
        :: "r"((uint32_t)__cvta_generic_to_shared(dst_half_ptr)), "l"(src_ptr))

// ---------------------------------------------------------------------------
// combine kernels (fp32 outputs)
// ---------------------------------------------------------------------------
__global__ void combine_compress_kernel(const float* __restrict__ w,
                                        const int*   __restrict__ idx,
                                        const float* __restrict__ cn,
                                        float*       __restrict__ Wc)
{
    int b = blockIdx.x >> 10;
    int d = blockIdx.x & 1023;
    int r = threadIdx.x;

    __shared__ float sw[KC];
    __shared__ int   si[KC];
    if (r < KC) { sw[r] = w[b * KC + r]; si[r] = idx[b * KC + r]; }
    __syncthreads();

    float acc = 0.f;
#pragma unroll
    for (int k = 0; k < KC; k++)
        acc += sw[k] * cn[((long)si[k] * D + d) * R + r];
    Wc[((long)b * D + d) * R + r] = acc;
}

__global__ void combine_expand_kernel(const float* __restrict__ wq, const int* __restrict__ iq,
                                      const float* __restrict__ wk, const int* __restrict__ ik,
                                      const float* __restrict__ wv, const int* __restrict__ iv,
                                      const float* __restrict__ pool,
                                      float* __restrict__ Wq, float* __restrict__ Wk,
                                      float* __restrict__ Wv)
{
    int mat = blockIdx.y;
    int br  = blockIdx.x;
    int b   = br >> 7;
    int r   = br & 127;

    const float* w   = (mat == 0) ? wq : (mat == 1) ? wk : wv;
    const int*   id  = (mat == 0) ? iq : (mat == 1) ? ik : iv;
    float*       out = (mat == 0) ? Wq : (mat == 1) ? Wk : Wv;

    __shared__ float sw[KE];
    __shared__ int   si[KE];
    int tid = threadIdx.x;
    if (tid < KE) { sw[tid] = w[b * KE + tid]; si[tid] = id[b * KE + tid]; }
    __syncthreads();

    int d0 = tid * 4;
    float4 acc = make_float4(0.f, 0.f, 0.f, 0.f);
#pragma unroll
    for (int k = 0; k < KE; k++) {
        float4 v = *(const float4*)&pool[((long)si[k] * R + r) * D + d0];
        float ww = sw[k];
        acc.x += ww * v.x; acc.y += ww * v.y;
        acc.z += ww * v.z; acc.w += ww * v.w;
    }
    *(float4*)&out[((long)b * R + r) * D + d0] = acc;
}

// ---------------------------------------------------------------------------
// fp32 [X][Y] -> fp16 hi/lo [Y][X] per batch z
// ---------------------------------------------------------------------------
__global__ void transpose_split_kernel(const float* __restrict__ in,
                                       __half* __restrict__ ohi,
                                       __half* __restrict__ olo, int X, int Y)
{
    __shared__ float t[32][33];
    long off = (long)blockIdx.z * X * Y;
    in += off; ohi += off; olo += off;
    int x0 = blockIdx.y * 32, y0 = blockIdx.x * 32;
    int tx = threadIdx.x, ty = threadIdx.y;
#pragma unroll
    for (int i = 0; i < 32; i += 8)
        t[ty + i][tx] = in[(long)(x0 + ty + i) * Y + y0 + tx];
    __syncthreads();
#pragma unroll
    for (int i = 0; i < 32; i += 8) {
        float v = t[tx][ty + i];
        __half h = __float2half_rn(v);
        long o = (long)(y0 + ty + i) * X + x0 + tx;
        ohi[o] = h;
        olo[o] = __float2half_rn(v - __half2float(h));
    }
}

// fp32 -> fp16 hi/lo, same layout
__global__ void split_kernel(const float* __restrict__ in,
                             __half* __restrict__ hi, __half* __restrict__ lo)
{
    long i = ((long)blockIdx.x * 256 + threadIdx.x) * 4;
    float4 v = *(const float4*)&in[i];
    uint32_t h0, l0, h1, l1;
    split2(v.x, v.y, h0, l0);
    split2(v.z, v.w, h1, l1);
    *(uint2*)&hi[i] = make_uint2(h0, h1);
    *(uint2*)&lo[i] = make_uint2(l0, l1);
}

// ---------------------------------------------------------------------------
// fp16-pair tensor-core GEMM (3-product, near-fp32):
//   C[M,N] = A[M,K] @ B[N,K]^T, operands pre-split (hi,lo) fp16 K-major.
// BM=BN=128, BK=32, 256 threads (2M x 4N warps, warp tile 64x32).
// Double-buffered cp.async; tiles [128][40] halves (pad -> conflict-free).
// grid (N/128, M/128, batches)
// ---------------------------------------------------------------------------
static constexpr int TILE_H    = 128 * 40;          // halves per tile
static constexpr int GEMM_SMEM = 2 * 4 * TILE_H * 2;  // 81920 B

template <bool SPLIT_OUT>
__global__ void __launch_bounds__(256)
hgemm(const __half* __restrict__ Ahi, const __half* __restrict__ Alo,
      const __half* __restrict__ Bhi, const __half* __restrict__ Blo,
      float* __restrict__ C, __half* __restrict__ Chi, __half* __restrict__ Clo,
      int K, int lda, int ldb, int ldc, long sA, long sB, long sC)
{
    extern __shared__ __half sm[];
    int tid = threadIdx.x, wid = tid >> 5, lane = tid & 31;
    int wm = wid & 1, wn = wid >> 1;
    int qr = lane >> 2, qc = lane & 3;

    long zA = (long)blockIdx.z * sA, zB = (long)blockIdx.z * sB, zC = (long)blockIdx.z * sC;
    int m0 = blockIdx.y * 128, n0 = blockIdx.x * 128;

    const __half* srcs[4] = { Ahi + zA, Alo + zA, Bhi + zB, Blo + zB };
    int rbase[4] = { m0, m0, n0, n0 };
    int lds[4]   = { lda, lda, ldb, ldb };

    float acc[4][4][4];
#pragma unroll
    for (int mi = 0; mi < 4; mi++)
#pragma unroll
        for (int ni = 0; ni < 4; ni++)
#pragma unroll
            for (int c = 0; c < 4; c++) acc[mi][ni][c] = 0.f;

    int nt = K / 32;

    auto load_stage = [&](int kt, int st) {
        __half* sb = sm + st * 4 * TILE_H;
#pragma unroll
        for (int i = 0; i < 8; i++) {
            int g = tid + i * 256;               // 0..2047
            int tsr = g >> 9;
            int rem = g & 511;
            int row = rem >> 2, ch = rem & 3;
            __half* dst = sb + tsr * TILE_H + row * 40 + ch * 8;
            const __half* src = srcs[tsr] + (long)(rbase[tsr] + row) * lds[tsr]
                                + kt * 32 + ch * 8;
            CP16(dst, src);
        }
        asm volatile("cp.async.commit_group;" ::: "memory");
    };

    load_stage(0, 0);

    for (int kt = 0; kt < nt; kt++) {
        if (kt + 1 < nt) {
            load_stage(kt + 1, (kt + 1) & 1);
            asm volatile("cp.async.wait_group 1;" ::: "memory");
        } else {
            asm volatile("cp.async.wait_group 0;" ::: "memory");
        }
        __syncthreads();

        const __half* sb = sm + (kt & 1) * 4 * TILE_H;
        const __half* As_hi = sb;
        const __half* As_lo = sb + TILE_H;
        const __half* Bs_hi = sb + 2 * TILE_H;
        const __half* Bs_lo = sb + 3 * TILE_H;

#pragma unroll
        for (int ks = 0; ks < 2; ks++) {
            uint32_t ahi[4][4], alo[4][4];
#pragma unroll
            for (int mi = 0; mi < 4; mi++) {
                int base = (wm * 64 + mi * 16 + qr) * 40 + ks * 16 + qc * 2;
                ahi[mi][0] = *(const uint32_t*)&As_hi[base];
                ahi[mi][1] = *(const uint32_t*)&As_hi[base + 8 * 40];
                ahi[mi][2] = *(const uint32_t*)&As_hi[base + 8];
                ahi[mi][3] = *(const uint32_t*)&As_hi[base + 8 * 40 + 8];
                alo[mi][0] = *(const uint32_t*)&As_lo[base];
                alo[mi][1] = *(const uint32_t*)&As_lo[base + 8 * 40];
                alo[mi][2] = *(const uint32_t*)&As_lo[base + 8];
                alo[mi][3] = *(const uint32_t*)&As_lo[base + 8 * 40 + 8];
            }
            uint32_t bhi[4][2], blo[4][2];
#pragma unroll
            for (int ni = 0; ni < 4; ni++) {
                int base = (wn * 32 + ni * 8 + qr) * 40 + ks * 16 + qc * 2;
                bhi[ni][0] = *(const uint32_t*)&Bs_hi[base];
                bhi[ni][1] = *(const uint32_t*)&Bs_hi[base + 8];
                blo[ni][0] = *(const uint32_t*)&Bs_lo[base];
                blo[ni][1] = *(const uint32_t*)&Bs_lo[base + 8];
            }
#pragma unroll
            for (int mi = 0; mi < 4; mi++)
#pragma unroll
                for (int ni = 0; ni < 4; ni++) {
                    MMA_F16(acc[mi][ni], alo[mi][0], alo[mi][1], alo[mi][2], alo[mi][3],
                            bhi[ni][0], bhi[ni][1]);
                    MMA_F16(acc[mi][ni], ahi[mi][0], ahi[mi][1], ahi[mi][2], ahi[mi][3],
                            blo[ni][0], blo[ni][1]);
                    MMA_F16(acc[mi][ni], ahi[mi][0], ahi[mi][1], ahi[mi][2], ahi[mi][3],
                            bhi[ni][0], bhi[ni][1]);
                }
        }
        __syncthreads();
    }

    // ---- epilogue ----
#pragma unroll
    for (int mi = 0; mi < 4; mi++) {
        int row = m0 + wm * 64 + mi * 16 + qr;
#pragma unroll
        for (int ni = 0; ni < 4; ni++) {
            int col = n0 + wn * 32 + ni * 8 + qc * 2;
            if (SPLIT_OUT) {
                uint32_t h, l;
                split2(acc[mi][ni][0], acc[mi][ni][1], h, l);
                *(uint32_t*)&Chi[zC + (long)row * ldc + col] = h;
                *(uint32_t*)&Clo[zC + (long)row * ldc + col] = l;
                split2(acc[mi][ni][2], acc[mi][ni][3], h, l);
                *(uint32_t*)&Chi[zC + (long)(row + 8) * ldc + col] = h;
                *(uint32_t*)&Clo[zC + (long)(row + 8) * ldc + col] = l;
            } else {
                *(float2*)&C[zC + (long)row * ldc + col] =
                    make_float2(acc[mi][ni][0], acc[mi][ni][1]);
                *(float2*)&C[zC + (long)(row + 8) * ldc + col] =
                    make_float2(acc[mi][ni][2], acc[mi][ni][3]);
            }
        }
    }
}

// ---------------------------------------------------------------------------
// Tensor-core causal flash attention (fp16-pair, 3-product).
// Block = 4 warps, QT=64 (warp: 16 rows), KT=64, DH=64.
// Q/K frag via padded LDS; V frag via ldmatrix.trans on swizzled tile.
// Writes AO as fp16 hi/lo. grid (S/64, H, B), 128 threads.
// Smem (halves): Qhi 4608 | Qlo 4608 | Khi 4608 | Klo 4608 | Vhi 4096 | Vlo 4096
// ---------------------------------------------------------------------------
static constexpr int FA_QHI = 0, FA_QLO = 4608, FA_KHI = 9216, FA_KLO = 13824,
                     FA_VHI = 18432, FA_VLO = 22528, FA_HALVES = 26624;
static constexpr int FLASH_SMEM = FA_HALVES * 2;   // 53248 B

__global__ void __launch_bounds__(128)
flash_mma(const __half* __restrict__ Qhi, const __half* __restrict__ Qlo,
          const __half* __restrict__ Khi, const __half* __restrict__ Klo,
          const __half* __restrict__ Vhi, const __half* __restrict__ Vlo,
          __half* __restrict__ AOhi, __half* __restrict__ AOlo)
{
    extern __shared__ __half sm[];
    int qt = blockIdx.x, h = blockIdx.y, b = blockIdx.z;
    int q0 = qt * 64;
    int tid = threadIdx.x, w = tid >> 5, lane = tid & 31;
    int qr = lane >> 2, qc = lane & 3;
    int rb = w * 16;

    const long bOff = (long)b * S * D;
    const __half* Qh = Qhi + bOff + (long)q0 * D + h * 64;
    const __half* Ql = Qlo + bOff + (long)q0 * D + h * 64;
    const __half* Kh = Khi + bOff + h * 64;
    const __half* Kl = Klo + bOff + h * 64;
    const __half* Vh = Vhi + bOff + h * 64;
    const __half* Vl = Vlo + bOff + h * 64;

    auto load_q = [&]() {
#pragma unroll
        for (int i = 0; i < 8; i++) {
            int g = tid + i * 128;               // 0..1023
            int tsr = g >> 9, rem = g & 511;
            int row = rem >> 3, ch = rem & 7;
            __half* dst = sm + (tsr ? FA_QLO : FA_QHI) + row * 72 + ch * 8;
            const __half* src = (tsr ? Ql : Qh) + (long)row * D + ch * 8;
            CP16(dst, src);
        }
    };
    auto load_kv = [&](int kt) {
#pragma unroll
        for (int i = 0; i < 16; i++) {
            int g = tid + i * 128;               // 0..2047
            int tsr = g >> 9, rem = g & 511;
            int row = rem >> 3, ch = rem & 7;
            __half* dst;
            const __half* src;
            if (tsr < 2) {                        // K: padded
                dst = sm + (tsr ? FA_KLO : FA_KHI) + row * 72 + ch * 8;
                src = (tsr ? Kl : Kh) + (long)(kt * 64 + row) * D + ch * 8;
            } else {                              // V: 128B-swizzled
                int col = (ch * 8) ^ ((row & 7) << 3);
                dst = sm + (tsr == 3 ? FA_VLO : FA_VHI) + row * 64 + col;
                src = (tsr == 3 ? Vl : Vh) + (long)(kt * 64 + row) * D + ch * 8;
            }
            CP16(dst, src);
        }
        asm volatile("cp.async.commit_group;" ::: "memory");
    };

    load_q();
    load_kv(0);
    asm volatile("cp.async.wait_group 0;" ::: "memory");
    __syncthreads();

    // preload Q fragments (held in regs across all tiles)
    uint32_t qa_hi[4][4], qa_lo[4][4];
#pragma unroll
    for (int j = 0; j < 4; j++) {
        int base0 = (rb + qr) * 72 + j * 16 + qc * 2;
#pragma unroll
        for (int r = 0; r < 4; r++) {
            int off = base0 + (r & 1) * 8 * 72 + (r >> 1) * 8;
            qa_hi[j][r] = *(const uint32_t*)&sm[FA_QHI + off];
            qa_lo[j][r] = *(const uint32_t*)&sm[FA_QLO + off];
        }
    }

    float o[8][4];
#pragma unroll
    for (int n = 0; n < 8; n++)
#pragma unroll
        for (int c = 0; c < 4; c++) o[n][c] = 0.f;
    float m0 = -1e30f, m1 = -1e30f, l0 = 0.f, l1 = 0.f;

    const float scale = 0.125f;
    int row0 = q0 + rb + qr, row1 = row0 + 8;
    int nkt = qt + 1;

    for (int kt = 0; kt < nkt; kt++) {
        // ---- S = Q K^T (3-product) ----
        float s[8][4];
#pragma unroll
        for (int n = 0; n < 8; n++)
#pragma unroll
            for (int c = 0; c < 4; c++) s[n][c] = 0.f;

#pragma unroll
        for (int n = 0; n < 8; n++) {
#pragma unroll
            for (int j = 0; j < 4; j++) {
                int base = (n * 8 + qr) * 72 + j * 16 + qc * 2;
                uint32_t bh0 = *(const uint32_t*)&sm[FA_KHI + base];
                uint32_t bh1 = *(const uint32_t*)&sm[FA_KHI + base + 8];
                uint32_t bl0 = *(const uint32_t*)&sm[FA_KLO + base];
                uint32_t bl1 = *(const uint32_t*)&sm[FA_KLO + base + 8];
                MMA_F16(s[n], qa_lo[j][0], qa_lo[j][1], qa_lo[j][2], qa_lo[j][3], bh0, bh1);
                MMA_F16(s[n], qa_hi[j][0], qa_hi[j][1], qa_hi[j][2], qa_hi[j][3], bl0, bl1);
                MMA_F16(s[n], qa_hi[j][0], qa_hi[j][1], qa_hi[j][2], qa_hi[j][3], bh0, bh1);
            }
        }

        // ---- mask + scale + online softmax ----
        float tm0 = -1e30f, tm1 = -1e30f;
#pragma unroll
        for (int n = 0; n < 8; n++) {
            int cb = kt * 64 + n * 8 + qc * 2;
            s[n][0] = (cb     > row0) ? -1e30f : s[n][0] * scale;
            s[n][1] = (cb + 1 > row0) ? -1e30f : s[n][1] * scale;
            s[n][2] = (cb     > row1) ? -1e30f : s[n][2] * scale;
            s[n][3] = (cb + 1 > row1) ? -1e30f : s[n][3] * scale;
            tm0 = fmaxf(tm0, fmaxf(s[n][0], s[n][1]));
            tm1 = fmaxf(tm1, fmaxf(s[n][2], s[n][3]));
        }
        tm0 = fmaxf(tm0, __shfl_xor_sync(0xffffffffu, tm0, 1));
        tm0 = fmaxf(tm0, __shfl_xor_sync(0xffffffffu, tm0, 2));
        tm1 = fmaxf(tm1, __shfl_xor_sync(0xffffffffu, tm1, 1));
        tm1 = fmaxf(tm1, __shfl_xor_sync(0xffffffffu, tm1, 2));

        float mn0 = fmaxf(m0, tm0), mn1 = fmaxf(m1, tm1);
        float al0 = __expf(m0 - mn0), al1 = __expf(m1 - mn1);
        m0 = mn0; m1 = mn1;

        float rs0 = 0.f, rs1 = 0.f;
#pragma unroll
        for (int n = 0; n < 8; n++) {
            s[n][0] = __expf(s[n][0] - mn0);
            s[n][1] = __expf(s[n][1] - mn0);
            s[n][2] = __expf(s[n][2] - mn1);
            s[n][3] = __expf(s[n][3] - mn1);
            rs0 += s[n][0] + s[n][1];
            rs1 += s[n][2] + s[n][3];
        }
        rs0 += __shfl_xor_sync(0xffffffffu, rs0, 1);
        rs0 += __shfl_xor_sync(0xffffffffu, rs0, 2);
        rs1 += __shfl_xor_sync(0xffffffffu, rs1, 1);
        rs1 += __shfl_xor_sync(0xffffffffu, rs1, 2);
        l0 = l0 * al0 + rs0;
        l1 = l1 * al1 + rs1;
#pragma unroll
        for (int n = 0; n < 8; n++) {
            o[n][0] *= al0; o[n][1] *= al0;
            o[n][2] *= al1; o[n][3] *= al1;
        }

        // ---- O += P V (3-product; P frags come from S frags) ----
#pragma unroll
        for (int j = 0; j < 4; j++) {
            uint32_t phi[4], plo[4];
            split2(s[2 * j][0],     s[2 * j][1],     phi[0], plo[0]);
            split2(s[2 * j][2],     s[2 * j][3],     phi[1], plo[1]);
            split2(s[2 * j + 1][0], s[2 * j + 1][1], phi[2], plo[2]);
            split2(s[2 * j + 1][2], s[2 * j + 1][3], phi[3], plo[3]);
            int kr = j * 16 + (lane & 15);
#pragma unroll
            for (int np = 0; np < 4; np++) {
                int nb = np * 16 + (lane >> 4) * 8;
                uint32_t addr_h = (uint32_t)__cvta_generic_to_shared(
                    &sm[FA_VHI + kr * 64 + (nb ^ ((kr & 7) << 3))]);
                uint32_t addr_l = (uint32_t)__cvta_generic_to_shared(
                    &sm[FA_VLO + kr * 64 + (nb ^ ((kr & 7) << 3))]);
                uint32_t vh[4], vl[4];
                asm volatile("ldmatrix.sync.aligned.m8n8.x4.trans.shared.b16 "
                             "{%0,%1,%2,%3}, [%4];"
                             : "=r"(vh[0]), "=r"(vh[1]), "=r"(vh[2]), "=r"(vh[3])
                             : "r"(addr_h));
                asm volatile("ldmatrix.sync.aligned.m8n8.x4.trans.shared.b16 "
                             "{%0,%1,%2,%3}, [%4];"
                             : "=r"(vl[0]), "=r"(vl[1]), "=r"(vl[2]), "=r"(vl[3])
                             : "r"(addr_l));
                int n0i = np * 2, n1i = np * 2 + 1;
                MMA_F16(o[n0i], plo[0], plo[1], plo[2], plo[3], vh[0], vh[1]);
                MMA_F16(o[n0i], phi[0], phi[1], phi[2], phi[3], vl[0], vl[1]);
                MMA_F16(o[n0i], phi[0], phi[1], phi[2], phi[3], vh[0], vh[1]);
                MMA_F16(o[n1i], plo[0], plo[1], plo[2], plo[3], vh[2], vh[3]);
                MMA_F16(o[n1i], phi[0], phi[1], phi[2], phi[3], vl[2], vl[3]);
                MMA_F16(o[n1i], phi[0], phi[1], phi[2], phi[3], vh[2], vh[3]);
            }
        }

        __syncthreads();
        if (kt + 1 < nkt) {
            load_kv(kt + 1);
            asm volatile("cp.async.wait_group 0;" ::: "memory");
            __syncthreads();
        }
    }

    // ---- epilogue: normalize, split, store ----
    float inv0 = 1.0f / l0, inv1 = 1.0f / l1;
    long obase = bOff + (long)h * 64;
#pragma unroll
    for (int n = 0; n < 8; n++) {
        int col = n * 8 + qc * 2;
        uint32_t hv, lv;
        split2(o[n][0] * inv0, o[n][1] * inv0, hv, lv);
        *(uint32_t*)&AOhi[obase + (long)row0 * D + col] = hv;
        *(uint32_t*)&AOlo[obase + (long)row0 * D + col] = lv;
        split2(o[n][2] * inv1, o[n][3] * inv1, hv, lv);
        *(uint32_t*)&AOhi[obase + (long)row1 * D + col] = hv;
        *(uint32_t*)&AOlo[obase + (long)row1 * D + col] = lv;
    }
}

// ---------------------------------------------------------------------------
// Host entry
// ---------------------------------------------------------------------------
extern "C" void kernel_launch(void* const* d_in, const int* in_sizes, int n_in,
                              void* d_out, int out_size)
{
    const float* x    = (const float*)d_in[0];
    const float* cw   = (const float*)d_in[1];
    const int*   ci   = (const int*)  d_in[2];
    const float* wq   = (const float*)d_in[3];
    const int*   iq   = (const int*)  d_in[4];
    const float* wk   = (const float*)d_in[5];
    const int*   ik   = (const int*)  d_in[6];
    const float* wv   = (const float*)d_in[7];
    const int*   iv   = (const int*)  d_in[8];
    const float* cn   = (const float*)d_in[9];
    const float* pool = (const float*)d_in[10];
    const float* WO   = (const float*)d_in[11];
    float* out = (float*)d_out;

    float* base = nullptr;
    cudaGetSymbolAddress((void**)&base, g_scratch);

    float*  Wc    = base;
    float*  Wqkv  = Wc + N_WC;                     // Wq|Wk|Wv fp32
    __half* hb    = (__half*)(Wqkv + 3 * N_WX);
    __half* xhi   = hb;               __half* xlo   = xhi   + N_QKV;
    __half* WcThi = xlo   + N_QKV;    __half* WcTlo = WcThi + N_WC;
    __half* WqThi = WcTlo + N_WC;     __half* WqTlo = WqThi + 3 * N_WX;
    __half* hhi   = WqTlo + 3 * N_WX; __half* hlo   = hhi   + N_H;
    __half* Qhi   = hlo   + N_H;      __half* Qlo   = Qhi   + N_QKV;
    __half* Khi   = Qlo   + N_QKV;    __half* Klo   = Khi   + N_QKV;
    __half* Vhi   = Klo   + N_QKV;    __half* Vlo   = Vhi   + N_QKV;
    __half* AOhi  = Vlo   + N_QKV;    __half* AOlo  = AOhi  + N_QKV;
    __half* WOhi  = AOlo  + N_QKV;    __half* WOlo  = WOhi  + N_WO;

    cudaFuncSetAttribute(hgemm<true>,
                         cudaFuncAttributeMaxDynamicSharedMemorySize, GEMM_SMEM);
    cudaFuncSetAttribute(hgemm<false>,
                         cudaFuncAttributeMaxDynamicSharedMemorySize, GEMM_SMEM);
    cudaFuncSetAttribute(flash_mma,
                         cudaFuncAttributeMaxDynamicSharedMemorySize, FLASH_SMEM);

    // 1) combines (fp32)
    combine_compress_kernel<<<B * D, 128>>>(cw, ci, cn, Wc);
    combine_expand_kernel<<<dim3(B * R, 3), 256>>>(wq, iq, wk, ik, wv, iv, pool,
                                                   Wqkv, Wqkv + N_WX, Wqkv + 2 * N_WX);

    // 2) splits: x, WO elementwise; Wc/Wqkv transpose+split into [N][K]
    split_kernel<<<(int)(N_QKV / 1024), 256>>>(x, xhi, xlo);
    split_kernel<<<(int)(N_WO  / 1024), 256>>>(WO, WOhi, WOlo);
    transpose_split_kernel<<<dim3(R / 32, D / 32, B), dim3(32, 8)>>>(Wc, WcThi, WcTlo, D, R);
    transpose_split_kernel<<<dim3(D / 32, R / 32, 3 * B), dim3(32, 8)>>>(Wqkv, WqThi, WqTlo, R, D);

    // 3) h = x @ WcT^T (M=S, N=R, K=D) -> split h
    hgemm<true><<<dim3(1, S / 128, B), 256, GEMM_SMEM>>>(
        xhi, xlo, WcThi, WcTlo, nullptr, hhi, hlo,
        D, D, D, R, (long)S * D, (long)R * D, (long)S * R);

    // 4) Q/K/V = h @ WxT^T (M=S, N=D, K=R) -> split outputs
    hgemm<true><<<dim3(D / 128, S / 128, B), 256, GEMM_SMEM>>>(
        hhi, hlo, WqThi, WqTlo, nullptr, Qhi, Qlo,
        R, R, R, D, (long)S * R, (long)D * R, (long)S * D);
    hgemm<true><<<dim3(D / 128, S / 128, B), 256, GEMM_SMEM>>>(
        hhi, hlo, WqThi + N_WX, WqTlo + N_WX, nullptr, Khi, Klo,
        R, R, R, D, (long)S * R, (long)D * R, (long)S * D);
    hgemm<true><<<dim3(D / 128, S / 128, B), 256, GEMM_SMEM>>>(
        hhi, hlo, WqThi + 2 * N_WX, WqTlo + 2 * N_WX, nullptr, Vhi, Vlo,
        R, R, R, D, (long)S * R, (long)D * R, (long)S * D);

    // 5) tensor-core causal flash attention -> AO split
    flash_mma<<<dim3(S / 64, H, B), 128, FLASH_SMEM>>>(
        Qhi, Qlo, Khi, Klo, Vhi, Vlo, AOhi, AOlo);

    // 6) out = AO @ W_O^T (M=B*S, N=D, K=D), fp32 out
    hgemm<false><<<dim3(D / 128, (B * S) / 128, 1), 256, GEMM_SMEM>>>(
        AOhi, AOlo, WOhi, WOlo, out, nullptr, nullptr,
        D, D, D, D, 0, 0, 0);
}

// round 12
// speedup vs baseline: 2.8544x; 1.1762x over previous
#include <cuda_runtime.h>
#include <cuda_fp16.h>
#include <cstdint>

// ---------------------------------------------------------------------------
// Problem constants
// ---------------------------------------------------------------------------
static constexpr int B   = 8;
static constexpr int S   = 1024;
static constexpr int D   = 1024;
static constexpr int H   = 16;
static constexpr int DH  = 64;
static constexpr int R   = 128;   // RANK
static constexpr int KC  = 16;
static constexpr int KE  = 8;

// ---------------------------------------------------------------------------
// Scratch layout
// ---------------------------------------------------------------------------
static constexpr size_t N_WC  = (size_t)B * D * R;
static constexpr size_t N_H   = (size_t)B * S * R;
static constexpr size_t N_WX  = (size_t)B * R * D;
static constexpr size_t N_QKV = (size_t)B * S * D;
static constexpr size_t N_WO  = (size_t)D * D;
static constexpr size_t HALVES =
    10 * N_QKV + 2 * N_WC + 6 * N_WX + 2 * N_H + 2 * N_WO;
static constexpr size_t SCRATCH_FLOATS = N_WC + 3 * N_WX + (HALVES + 1) / 2;

__device__ __align__(1024) float g_scratch[SCRATCH_FLOATS];

// ---------------------------------------------------------------------------
// Helpers
// ---------------------------------------------------------------------------
__device__ __forceinline__ void split2(float a, float b, uint32_t& hi, uint32_t& lo) {
    __half2 h = __floats2half2_rn(a, b);
    hi = *reinterpret_cast<uint32_t*>(&h);
    float2 f = __half22float2(h);
    __half2 l = __floats2half2_rn(a - f.x, b - f.y);
    lo = *reinterpret_cast<uint32_t*>(&l);
}

#define MMA_F16(ACC, A0, A1, A2, A3, B0, B1)                                   \
    asm volatile("mma.sync.aligned.m16n8k16.row.col.f32.f16.f16.f32 "          \
        "{%0,%1,%2,%3}, {%4,%5,%6,%7}, {%8,%9}, {%0,%1,%2,%3};"                \
        : "+f"((ACC)[0]), "+f"((ACC)[1]), "+f"((ACC)[2]), "+f"((ACC)[3])       \
        : "r"(A0), "r"(A1), "r"(A2), "r"(A3), "r"(B0), "r"(B1))

#define CP16(dst_half_ptr, src_ptr)                                            \
    asm volatile("cp.async.cg.shared.global [%0], [%1], 16;"                   \
        :: "r"((uint32_t)__cvta_generic_to_shared(dst_half_ptr)), "l"(src_ptr))

// ---------------------------------------------------------------------------
// combine kernels (fp32 outputs)
// ---------------------------------------------------------------------------
__global__ void combine_compress_kernel(const float* __restrict__ w,
                                        const int*   __restrict__ idx,
                                        const float* __restrict__ cn,
                                        float*       __restrict__ Wc)
{
    int b = blockIdx.x >> 10;
    int d = blockIdx.x & 1023;
    int r = threadIdx.x;

    __shared__ float sw[KC];
    __shared__ int   si[KC];
    if (r < KC) { sw[r] = w[b * KC + r]; si[r] = idx[b * KC + r]; }
    __syncthreads();

    float acc = 0.f;
#pragma unroll
    for (int k = 0; k < KC; k++)
        acc += sw[k] * cn[((long)si[k] * D + d) * R + r];
    Wc[((long)b * D + d) * R + r] = acc;
}

__global__ void combine_expand_kernel(const float* __restrict__ wq, const int* __restrict__ iq,
                                      const float* __restrict__ wk, const int* __restrict__ ik,
                                      const float* __restrict__ wv, const int* __restrict__ iv,
                                      const float* __restrict__ pool,
                                      float* __restrict__ Wq, float* __restrict__ Wk,
                                      float* __restrict__ Wv)
{
    int mat = blockIdx.y;
    int br  = blockIdx.x;
    int b   = br >> 7;
    int r   = br & 127;

    const float* w   = (mat == 0) ? wq : (mat == 1) ? wk : wv;
    const int*   id  = (mat == 0) ? iq : (mat == 1) ? ik : iv;
    float*       out = (mat == 0) ? Wq : (mat == 1) ? Wk : Wv;

    __shared__ float sw[KE];
    __shared__ int   si[KE];
    int tid = threadIdx.x;
    if (tid < KE) { sw[tid] = w[b * KE + tid]; si[tid] = id[b * KE + tid]; }
    __syncthreads();

    int d0 = tid * 4;
    float4 acc = make_float4(0.f, 0.f, 0.f, 0.f);
#pragma unroll
    for (int k = 0; k < KE; k++) {
        float4 v = *(const float4*)&pool[((long)si[k] * R + r) * D + d0];
        float ww = sw[k];
        acc.x += ww * v.x; acc.y += ww * v.y;
        acc.z += ww * v.z; acc.w += ww * v.w;
    }
    *(float4*)&out[((long)b * R + r) * D + d0] = acc;
}

// ---------------------------------------------------------------------------
// fp32 [X][Y] -> fp16 hi/lo [Y][X] per batch z
// ---------------------------------------------------------------------------
__global__ void transpose_split_kernel(const float* __restrict__ in,
                                       __half* __restrict__ ohi,
                                       __half* __restrict__ olo, int X, int Y)
{
    __shared__ float t[32][33];
    long off = (long)blockIdx.z * X * Y;
    in += off; ohi += off; olo += off;
    int x0 = blockIdx.y * 32, y0 = blockIdx.x * 32;
    int tx = threadIdx.x, ty = threadIdx.y;
#pragma unroll
    for (int i = 0; i < 32; i += 8)
        t[ty + i][tx] = in[(long)(x0 + ty + i) * Y + y0 + tx];
    __syncthreads();
#pragma unroll
    for (int i = 0; i < 32; i += 8) {
        float v = t[tx][ty + i];
        __half h = __float2half_rn(v);
        long o = (long)(y0 + ty + i) * X + x0 + tx;
        ohi[o] = h;
        olo[o] = __float2half_rn(v - __half2float(h));
    }
}

__global__ void split_kernel(const float* __restrict__ in,
                             __half* __restrict__ hi, __half* __restrict__ lo)
{
    long i = ((long)blockIdx.x * 256 + threadIdx.x) * 4;
    float4 v = *(const float4*)&in[i];
    uint32_t h0, l0, h1, l1;
    split2(v.x, v.y, h0, l0);
    split2(v.z, v.w, h1, l1);
    *(uint2*)&hi[i] = make_uint2(h0, h1);
    *(uint2*)&lo[i] = make_uint2(l0, l1);
}

// ---------------------------------------------------------------------------
// fp16-pair tensor-core GEMM:
//   C[M,N] = A[M,K] @ B[N,K]^T, operands pre-split (hi,lo) fp16 K-major.
// NPROD=3: hh + hl + lh (near-fp32). NPROD=2: hh + lh (drops Ahi*Blo; B-lo
// tile never loaded). BM=BN=128, BK=32, 256 threads (2Mx4N warps).
// ---------------------------------------------------------------------------
static constexpr int TILE_H    = 128 * 40;
static constexpr int GEMM_SMEM = 2 * 4 * TILE_H * 2;  // 81920 B

template <int NPROD, bool SPLIT_OUT>
__global__ void __launch_bounds__(256)
hgemm(const __half* __restrict__ Ahi, const __half* __restrict__ Alo,
      const __half* __restrict__ Bhi, const __half* __restrict__ Blo,
      float* __restrict__ C, __half* __restrict__ Chi, __half* __restrict__ Clo,
      int K, int lda, int ldb, int ldc, long sA, long sB, long sC)
{
    extern __shared__ __half sm[];
    int tid = threadIdx.x, wid = tid >> 5, lane = tid & 31;
    int wm = wid & 1, wn = wid >> 1;
    int qr = lane >> 2, qc = lane & 3;

    long zA = (long)blockIdx.z * sA, zB = (long)blockIdx.z * sB, zC = (long)blockIdx.z * sC;
    int m0 = blockIdx.y * 128, n0 = blockIdx.x * 128;

    const __half* srcs[4] = { Ahi + zA, Alo + zA, Bhi + zB, Blo + zB };
    int rbase[4] = { m0, m0, n0, n0 };
    int lds[4]   = { lda, lda, ldb, ldb };

    float acc[4][4][4];
#pragma unroll
    for (int mi = 0; mi < 4; mi++)
#pragma unroll
        for (int ni = 0; ni < 4; ni++)
#pragma unroll
            for (int c = 0; c < 4; c++) acc[mi][ni][c] = 0.f;

    int nt = K / 32;
    constexpr int NLOAD = (NPROD == 3) ? 8 : 6;   // tensors to stage

    auto load_stage = [&](int kt, int st) {
        __half* sb = sm + st * 4 * TILE_H;
#pragma unroll
        for (int i = 0; i < NLOAD; i++) {
            int g = tid + i * 256;
            int tsr = g >> 9;
            int rem = g & 511;
            int row = rem >> 2, ch = rem & 3;
            __half* dst = sb + tsr * TILE_H + row * 40 + ch * 8;
            const __half* src = srcs[tsr] + (long)(rbase[tsr] + row) * lds[tsr]
                                + kt * 32 + ch * 8;
            CP16(dst, src);
        }
        asm volatile("cp.async.commit_group;" ::: "memory");
    };

    load_stage(0, 0);

    for (int kt = 0; kt < nt; kt++) {
        if (kt + 1 < nt) {
            load_stage(kt + 1, (kt + 1) & 1);
            asm volatile("cp.async.wait_group 1;" ::: "memory");
        } else {
            asm volatile("cp.async.wait_group 0;" ::: "memory");
        }
        __syncthreads();

        const __half* sb = sm + (kt & 1) * 4 * TILE_H;
        const __half* As_hi = sb;
        const __half* As_lo = sb + TILE_H;
        const __half* Bs_hi = sb + 2 * TILE_H;
        const __half* Bs_lo = sb + 3 * TILE_H;

#pragma unroll
        for (int ks = 0; ks < 2; ks++) {
            uint32_t ahi[4][4], alo[4][4];
#pragma unroll
            for (int mi = 0; mi < 4; mi++) {
                int base = (wm * 64 + mi * 16 + qr) * 40 + ks * 16 + qc * 2;
                ahi[mi][0] = *(const uint32_t*)&As_hi[base];
                ahi[mi][1] = *(const uint32_t*)&As_hi[base + 8 * 40];
                ahi[mi][2] = *(const uint32_t*)&As_hi[base + 8];
                ahi[mi][3] = *(const uint32_t*)&As_hi[base + 8 * 40 + 8];
                alo[mi][0] = *(const uint32_t*)&As_lo[base];
                alo[mi][1] = *(const uint32_t*)&As_lo[base + 8 * 40];
                alo[mi][2] = *(const uint32_t*)&As_lo[base + 8];
                alo[mi][3] = *(const uint32_t*)&As_lo[base + 8 * 40 + 8];
            }
            uint32_t bhi[4][2], blo[4][2];
#pragma unroll
            for (int ni = 0; ni < 4; ni++) {
                int base = (wn * 32 + ni * 8 + qr) * 40 + ks * 16 + qc * 2;
                bhi[ni][0] = *(const uint32_t*)&Bs_hi[base];
                bhi[ni][1] = *(const uint32_t*)&Bs_hi[base + 8];
                if (NPROD == 3) {
                    blo[ni][0] = *(const uint32_t*)&Bs_lo[base];
                    blo[ni][1] = *(const uint32_t*)&Bs_lo[base + 8];
                }
            }
#pragma unroll
            for (int mi = 0; mi < 4; mi++)
#pragma unroll
                for (int ni = 0; ni < 4; ni++) {
                    MMA_F16(acc[mi][ni], alo[mi][0], alo[mi][1], alo[mi][2], alo[mi][3],
                            bhi[ni][0], bhi[ni][1]);
                    if (NPROD == 3)
                        MMA_F16(acc[mi][ni], ahi[mi][0], ahi[mi][1], ahi[mi][2], ahi[mi][3],
                                blo[ni][0], blo[ni][1]);
                    MMA_F16(acc[mi][ni], ahi[mi][0], ahi[mi][1], ahi[mi][2], ahi[mi][3],
                            bhi[ni][0], bhi[ni][1]);
                }
        }
        __syncthreads();
    }

    // ---- epilogue ----
#pragma unroll
    for (int mi = 0; mi < 4; mi++) {
        int row = m0 + wm * 64 + mi * 16 + qr;
#pragma unroll
        for (int ni = 0; ni < 4; ni++) {
            int col = n0 + wn * 32 + ni * 8 + qc * 2;
            if (SPLIT_OUT) {
                uint32_t h, l;
                split2(acc[mi][ni][0], acc[mi][ni][1], h, l);
                *(uint32_t*)&Chi[zC + (long)row * ldc + col] = h;
                *(uint32_t*)&Clo[zC + (long)row * ldc + col] = l;
                split2(acc[mi][ni][2], acc[mi][ni][3], h, l);
                *(uint32_t*)&Chi[zC + (long)(row + 8) * ldc + col] = h;
                *(uint32_t*)&Clo[zC + (long)(row + 8) * ldc + col] = l;
            } else {
                *(float2*)&C[zC + (long)row * ldc + col] =
                    make_float2(acc[mi][ni][0], acc[mi][ni][1]);
                *(float2*)&C[zC + (long)(row + 8) * ldc + col] =
                    make_float2(acc[mi][ni][2], acc[mi][ni][3]);
            }
        }
    }
}

// ---------------------------------------------------------------------------
// Tensor-core causal flash attention (fp16-pair).
// QK^T: 3-product (logit-sensitive). PV: 2-product (P hi+lo) x V_hi only —
// V_lo tile/loads dropped.
// Block = 4 warps, QT=64 (warp: 16 rows), KT=64, DH=64.
// Smem (halves): Qhi 4608 | Qlo 4608 | Khi 4608 | Klo 4608 | Vhi 4096
// ---------------------------------------------------------------------------
static constexpr int FA_QHI = 0, FA_QLO = 4608, FA_KHI = 9216, FA_KLO = 13824,
                     FA_VHI = 18432, FA_HALVES = 22528;
static constexpr int FLASH_SMEM = FA_HALVES * 2;   // 45056 B

__global__ void __launch_bounds__(128)
flash_mma(const __half* __restrict__ Qhi, const __half* __restrict__ Qlo,
          const __half* __restrict__ Khi, const __half* __restrict__ Klo,
          const __half* __restrict__ Vhi,
          __half* __restrict__ AOhi, __half* __restrict__ AOlo)
{
    extern __shared__ __half sm[];
    int qt = blockIdx.x, h = blockIdx.y, b = blockIdx.z;
    int q0 = qt * 64;
    int tid = threadIdx.x, w = tid >> 5, lane = tid & 31;
    int qr = lane >> 2, qc = lane & 3;
    int rb = w * 16;

    const long bOff = (long)b * S * D;
    const __half* Qh = Qhi + bOff + (long)q0 * D + h * 64;
    const __half* Ql = Qlo + bOff + (long)q0 * D + h * 64;
    const __half* Kh = Khi + bOff + h * 64;
    const __half* Kl = Klo + bOff + h * 64;
    const __half* Vh = Vhi + bOff + h * 64;

    auto load_q = [&]() {
#pragma unroll
        for (int i = 0; i < 8; i++) {
            int g = tid + i * 128;
            int tsr = g >> 9, rem = g & 511;
            int row = rem >> 3, ch = rem & 7;
            __half* dst = sm + (tsr ? FA_QLO : FA_QHI) + row * 72 + ch * 8;
            const __half* src = (tsr ? Ql : Qh) + (long)row * D + ch * 8;
            CP16(dst, src);
        }
    };
    auto load_kv = [&](int kt) {
#pragma unroll
        for (int i = 0; i < 12; i++) {
            int g = tid + i * 128;               // 0..1535, 3 tensors
            int tsr = g >> 9, rem = g & 511;
            int row = rem >> 3, ch = rem & 7;
            __half* dst;
            const __half* src;
            if (tsr < 2) {                        // K: padded
                dst = sm + (tsr ? FA_KLO : FA_KHI) + row * 72 + ch * 8;
                src = (tsr ? Kl : Kh) + (long)(kt * 64 + row) * D + ch * 8;
            } else {                              // V hi: 128B-swizzled
                int col = (ch * 8) ^ ((row & 7) << 3);
                dst = sm + FA_VHI + row * 64 + col;
                src = Vh + (long)(kt * 64 + row) * D + ch * 8;
            }
            CP16(dst, src);
        }
        asm volatile("cp.async.commit_group;" ::: "memory");
    };

    load_q();
    load_kv(0);
    asm volatile("cp.async.wait_group 0;" ::: "memory");
    __syncthreads();

    uint32_t qa_hi[4][4], qa_lo[4][4];
#pragma unroll
    for (int j = 0; j < 4; j++) {
        int base0 = (rb + qr) * 72 + j * 16 + qc * 2;
#pragma unroll
        for (int r = 0; r < 4; r++) {
            int off = base0 + (r & 1) * 8 * 72 + (r >> 1) * 8;
            qa_hi[j][r] = *(const uint32_t*)&sm[FA_QHI + off];
            qa_lo[j][r] = *(const uint32_t*)&sm[FA_QLO + off];
        }
    }

    float o[8][4];
#pragma unroll
    for (int n = 0; n < 8; n++)
#pragma unroll
        for (int c = 0; c < 4; c++) o[n][c] = 0.f;
    float m0 = -1e30f, m1 = -1e30f, l0 = 0.f, l1 = 0.f;

    const float scale = 0.125f;
    int row0 = q0 + rb + qr, row1 = row0 + 8;
    int nkt = qt + 1;

    for (int kt = 0; kt < nkt; kt++) {
        // ---- S = Q K^T (3-product) ----
        float s[8][4];
#pragma unroll
        for (int n = 0; n < 8; n++)
#pragma unroll
            for (int c = 0; c < 4; c++) s[n][c] = 0.f;

#pragma unroll
        for (int n = 0; n < 8; n++) {
#pragma unroll
            for (int j = 0; j < 4; j++) {
                int base = (n * 8 + qr) * 72 + j * 16 + qc * 2;
                uint32_t bh0 = *(const uint32_t*)&sm[FA_KHI + base];
                uint32_t bh1 = *(const uint32_t*)&sm[FA_KHI + base + 8];
                uint32_t bl0 = *(const uint32_t*)&sm[FA_KLO + base];
                uint32_t bl1 = *(const uint32_t*)&sm[FA_KLO + base + 8];
                MMA_F16(s[n], qa_lo[j][0], qa_lo[j][1], qa_lo[j][2], qa_lo[j][3], bh0, bh1);
                MMA_F16(s[n], qa_hi[j][0], qa_hi[j][1], qa_hi[j][2], qa_hi[j][3], bl0, bl1);
                MMA_F16(s[n], qa_hi[j][0], qa_hi[j][1], qa_hi[j][2], qa_hi[j][3], bh0, bh1);
            }
        }

        // ---- mask + scale + online softmax ----
        float tm0 = -1e30f, tm1 = -1e30f;
#pragma unroll
        for (int n = 0; n < 8; n++) {
            int cb = kt * 64 + n * 8 + qc * 2;
            s[n][0] = (cb     > row0) ? -1e30f : s[n][0] * scale;
            s[n][1] = (cb + 1 > row0) ? -1e30f : s[n][1] * scale;
            s[n][2] = (cb     > row1) ? -1e30f : s[n][2] * scale;
            s[n][3] = (cb + 1 > row1) ? -1e30f : s[n][3] * scale;
            tm0 = fmaxf(tm0, fmaxf(s[n][0], s[n][1]));
            tm1 = fmaxf(tm1, fmaxf(s[n][2], s[n][3]));
        }
        tm0 = fmaxf(tm0, __shfl_xor_sync(0xffffffffu, tm0, 1));
        tm0 = fmaxf(tm0, __shfl_xor_sync(0xffffffffu, tm0, 2));
        tm1 = fmaxf(tm1, __shfl_xor_sync(0xffffffffu, tm1, 1));
        tm1 = fmaxf(tm1, __shfl_xor_sync(0xffffffffu, tm1, 2));

        float mn0 = fmaxf(m0, tm0), mn1 = fmaxf(m1, tm1);
        float al0 = __expf(m0 - mn0), al1 = __expf(m1 - mn1);
        m0 = mn0; m1 = mn1;

        float rs0 = 0.f, rs1 = 0.f;
#pragma unroll
        for (int n = 0; n < 8; n++) {
            s[n][0] = __expf(s[n][0] - mn0);
            s[n][1] = __expf(s[n][1] - mn0);
            s[n][2] = __expf(s[n][2] - mn1);
            s[n][3] = __expf(s[n][3] - mn1);
            rs0 += s[n][0] + s[n][1];
            rs1 += s[n][2] + s[n][3];
        }
        rs0 += __shfl_xor_sync(0xffffffffu, rs0, 1);
        rs0 += __shfl_xor_sync(0xffffffffu, rs0, 2);
        rs1 += __shfl_xor_sync(0xffffffffu, rs1, 1);
        rs1 += __shfl_xor_sync(0xffffffffu, rs1, 2);
        l0 = l0 * al0 + rs0;
        l1 = l1 * al1 + rs1;
#pragma unroll
        for (int n = 0; n < 8; n++) {
            o[n][0] *= al0; o[n][1] *= al0;
            o[n][2] *= al1; o[n][3] *= al1;
        }

        // ---- O += P V_hi (2-product: (P_hi + P_lo) * V_hi) ----
#pragma unroll
        for (int j = 0; j < 4; j++) {
            uint32_t phi[4], plo[4];
            split2(s[2 * j][0],     s[2 * j][1],     phi[0], plo[0]);
            split2(s[2 * j][2],     s[2 * j][3],     phi[1], plo[1]);
            split2(s[2 * j + 1][0], s[2 * j + 1][1], phi[2], plo[2]);
            split2(s[2 * j + 1][2], s[2 * j + 1][3], phi[3], plo[3]);
            int kr = j * 16 + (lane & 15);
#pragma unroll
            for (int np = 0; np < 4; np++) {
                int nb = np * 16 + (lane >> 4) * 8;
                uint32_t addr_h = (uint32_t)__cvta_generic_to_shared(
                    &sm[FA_VHI + kr * 64 + (nb ^ ((kr & 7) << 3))]);
                uint32_t vh[4];
                asm volatile("ldmatrix.sync.aligned.m8n8.x4.trans.shared.b16 "
                             "{%0,%1,%2,%3}, [%4];"
                             : "=r"(vh[0]), "=r"(vh[1]), "=r"(vh[2]), "=r"(vh[3])
                             : "r"(addr_h));
                int n0i = np * 2, n1i = np * 2 + 1;
                MMA_F16(o[n0i], plo[0], plo[1], plo[2], plo[3], vh[0], vh[1]);
                MMA_F16(o[n0i], phi[0], phi[1], phi[2], phi[3], vh[0], vh[1]);
                MMA_F16(o[n1i], plo[0], plo[1], plo[2], plo[3], vh[2], vh[3]);
                MMA_F16(o[n1i], phi[0], phi[1], phi[2], phi[3], vh[2], vh[3]);
            }
        }

        __syncthreads();
        if (kt + 1 < nkt) {
            load_kv(kt + 1);
            asm volatile("cp.async.wait_group 0;" ::: "memory");
            __syncthreads();
        }
    }

    // ---- epilogue: normalize, split, store ----
    float inv0 = 1.0f / l0, inv1 = 1.0f / l1;
    long obase = bOff + (long)h * 64;
#pragma unroll
    for (int n = 0; n < 8; n++) {
        int col = n * 8 + qc * 2;
        uint32_t hv, lv;
        split2(o[n][0] * inv0, o[n][1] * inv0, hv, lv);
        *(uint32_t*)&AOhi[obase + (long)row0 * D + col] = hv;
        *(uint32_t*)&AOlo[obase + (long)row0 * D + col] = lv;
        split2(o[n][2] * inv1, o[n][3] * inv1, hv, lv);
        *(uint32_t*)&AOhi[obase + (long)row1 * D + col] = hv;
        *(uint32_t*)&AOlo[obase + (long)row1 * D + col] = lv;
    }
}

// ---------------------------------------------------------------------------
// Host entry
// ---------------------------------------------------------------------------
extern "C" void kernel_launch(void* const* d_in, const int* in_sizes, int n_in,
                              void* d_out, int out_size)
{
    const float* x    = (const float*)d_in[0];
    const float* cw   = (const float*)d_in[1];
    const int*   ci   = (const int*)  d_in[2];
    const float* wq   = (const float*)d_in[3];
    const int*   iq   = (const int*)  d_in[4];
    const float* wk   = (const float*)d_in[5];
    const int*   ik   = (const int*)  d_in[6];
    const float* wv   = (const float*)d_in[7];
    const int*   iv   = (const int*)  d_in[8];
    const float* cn   = (const float*)d_in[9];
    const float* pool = (const float*)d_in[10];
    const float* WO   = (const float*)d_in[11];
    float* out = (float*)d_out;

    float* base = nullptr;
    cudaGetSymbolAddress((void**)&base, g_scratch);

    float*  Wc    = base;
    float*  Wqkv  = Wc + N_WC;
    __half* hb    = (__half*)(Wqkv + 3 * N_WX);
    __half* xhi   = hb;               __half* xlo   = xhi   + N_QKV;
    __half* WcThi = xlo   + N_QKV;    __half* WcTlo = WcThi + N_WC;
    __half* WqThi = WcTlo + N_WC;     __half* WqTlo = WqThi + 3 * N_WX;
    __half* hhi   = WqTlo + 3 * N_WX; __half* hlo   = hhi   + N_H;
    __half* Qhi   = hlo   + N_H;      __half* Qlo   = Qhi   + N_QKV;
    __half* Khi   = Qlo   + N_QKV;    __half* Klo   = Khi   + N_QKV;
    __half* Vhi   = Klo   + N_QKV;    __half* Vlo   = Vhi   + N_QKV;
    __half* AOhi  = Vlo   + N_QKV;    __half* AOlo  = AOhi  + N_QKV;
    __half* WOhi  = AOlo  + N_QKV;    __half* WOlo  = WOhi  + N_WO;

    cudaFuncSetAttribute(hgemm<3, true>,
                         cudaFuncAttributeMaxDynamicSharedMemorySize, GEMM_SMEM);
    cudaFuncSetAttribute(hgemm<2, true>,
                         cudaFuncAttributeMaxDynamicSharedMemorySize, GEMM_SMEM);
    cudaFuncSetAttribute(hgemm<2, false>,
                         cudaFuncAttributeMaxDynamicSharedMemorySize, GEMM_SMEM);
    cudaFuncSetAttribute(flash_mma,
                         cudaFuncAttributeMaxDynamicSharedMemorySize, FLASH_SMEM);

    // 1) combines (fp32)
    combine_compress_kernel<<<B * D, 128>>>(cw, ci, cn, Wc);
    combine_expand_kernel<<<dim3(B * R, 3), 256>>>(wq, iq, wk, ik, wv, iv, pool,
                                                   Wqkv, Wqkv + N_WX, Wqkv + 2 * N_WX);

    // 2) splits
    split_kernel<<<(int)(N_QKV / 1024), 256>>>(x, xhi, xlo);
    split_kernel<<<(int)(N_WO  / 1024), 256>>>(WO, WOhi, WOlo);
    transpose_split_kernel<<<dim3(R / 32, D / 32, B), dim3(32, 8)>>>(Wc, WcThi, WcTlo, D, R);
    transpose_split_kernel<<<dim3(D / 32, R / 32, 3 * B), dim3(32, 8)>>>(Wqkv, WqThi, WqTlo, R, D);

    // 3) h = x @ WcT^T (3-product; feeds logit path)
    hgemm<3, true><<<dim3(1, S / 128, B), 256, GEMM_SMEM>>>(
        xhi, xlo, WcThi, WcTlo, nullptr, hhi, hlo,
        D, D, D, R, (long)S * D, (long)R * D, (long)S * R);

    // 4) Q/K 3-product (logit-sensitive); V 2-product
    hgemm<3, true><<<dim3(D / 128, S / 128, B), 256, GEMM_SMEM>>>(
        hhi, hlo, WqThi, WqTlo, nullptr, Qhi, Qlo,
        R, R, R, D, (long)S * R, (long)D * R, (long)S * D);
    hgemm<3, true><<<dim3(D / 128, S / 128, B), 256, GEMM_SMEM>>>(
        hhi, hlo, WqThi + N_WX, WqTlo + N_WX, nullptr, Khi, Klo,
        R, R, R, D, (long)S * R, (long)D * R, (long)S * D);
    hgemm<2, true><<<dim3(D / 128, S / 128, B), 256, GEMM_SMEM>>>(
        hhi, hlo, WqThi + 2 * N_WX, WqTlo + 2 * N_WX, nullptr, Vhi, Vlo,
        R, R, R, D, (long)S * R, (long)D * R, (long)S * D);

    // 5) flash attention (QK 3-product, PV 2-product)
    flash_mma<<<dim3(S / 64, H, B), 128, FLASH_SMEM>>>(
        Qhi, Qlo, Khi, Klo, Vhi, AOhi, AOlo);

    // 6) out = AO @ W_O^T (2-product; WO_lo unused)
    hgemm<2, false><<<dim3(D / 128, (B * S) / 128, 1), 256, GEMM_SMEM>>>(
        AOhi, AOlo, WOhi, WOlo, out, nullptr, nullptr,
        D, D, D, D, 0, 0, 0);
}